// round 13
// baseline (speedup 1.0000x reference)
#include <cuda_runtime.h>
#include <math.h>
#include <stdint.h>

#define Bsz 2
#define Lsz 1024
#define Dsz 1024
#define Hsz 16
#define Esz 64
#define NDsz 512
#define HDsz 64
#define QSCALE 0.125f   // 1/sqrt(64), exact power of two

// ----------------------------- scratch (device globals, no allocs) -----------------------------
__device__ float g_hn   [Bsz*Lsz*Dsz];
__device__ float g_sn   [Bsz*Lsz*NDsz];
__device__ float g_h2   [Bsz*Lsz*Dsz];
__device__ float g_qkvg [(size_t)Bsz*Lsz*4*Dsz];   // [2048][4096]: q|k|v|graw
__device__ float g_vt   [Bsz*Lsz*Dsz];             // V^T [B][D][L]
__device__ float g_yb   [Bsz*Lsz*Dsz];
__device__ float g_gate [Bsz*Lsz*Dsz];             // sigmoid(s@op_w+op_b)
__device__ float g_bias [(size_t)Bsz*Hsz*Lsz*Lsz]; // 128 MB, [b][h][i][j]
__device__ float g_wqkvg[Dsz*4*Dsz];               // [1024][4096] tf32-rounded
__device__ float g_bqkvg[4*Dsz];
__device__ float g_ws12i[NDsz*2*Dsz];              // [512][2048] interleaved, rounded
__device__ float g_bs12i[2*Dsz];
__device__ float g_wo   [Dsz*Dsz];                 // o_w rounded
__device__ float g_wop  [NDsz*Dsz];                // op_w rounded
__device__ float g_sr   [Bsz*Lsz*NDsz];            // s rounded

// ----------------------------- fast math -----------------------------
__device__ __forceinline__ float fexp(float x) {
    x = fminf(fmaxf(x, -80.f), 80.f);
    float t  = x * 1.44269504f;
    float fj = t + 12582912.f;
    int   i  = __float_as_int(fj) - 0x4B400000;
    float j  = fj - 12582912.f;
    float f  = t - j;
    float u  = f * 0.69314718f;
    float p  = 1.f + u * (1.f + u * (0.5f + u * (0.166666667f +
               u * (0.0416666667f + u * 0.00833333333f))));
    return p * __int_as_float((i + 127) << 23);
}
__device__ __forceinline__ float sigmoidf_(float x) {
    return __fdividef(1.0f, 1.0f + fexp(-x));
}
__device__ __forceinline__ float tf32r(float x) {
    uint32_t u;
    asm("cvt.rna.tf32.f32 %0, %1;" : "=r"(u) : "f"(x));
    return __uint_as_float(u);
}
__device__ __forceinline__ void mma8(float* d, const float* a, float b0f, float b1f) {
    const uint32_t* A = (const uint32_t*)a;
    uint32_t B0 = __float_as_uint(b0f), B1 = __float_as_uint(b1f);
    asm volatile(
        "mma.sync.aligned.m16n8k8.row.col.f32.tf32.tf32.f32 "
        "{%0,%1,%2,%3}, {%4,%5,%6,%7}, {%8,%9}, {%0,%1,%2,%3};\n"
        : "+f"(d[0]), "+f"(d[1]), "+f"(d[2]), "+f"(d[3])
        : "r"(A[0]), "r"(A[1]), "r"(A[2]), "r"(A[3]), "r"(B0), "r"(B1));
}

// ----------------------------- pack / convert kernels -----------------------------
__global__ void pack_s12(const float* __restrict__ s1w, const float* __restrict__ s2w,
                         const float* __restrict__ s1b, const float* __restrict__ s2b,
                         float* __restrict__ wi, float* __restrict__ bi) {
    int i = blockIdx.x * 256 + threadIdx.x;
    if (i < NDsz * Dsz) {
        int k = i >> 10, f = i & 1023;
        float2 v; v.x = tf32r(s1w[i]); v.y = tf32r(s2w[i]);
        *(float2*)(wi + (size_t)k * 2048 + 2 * f) = v;
    }
    if (i < Dsz) { bi[2 * i] = s1b[i]; bi[2 * i + 1] = s2b[i]; }
}
__global__ void pack_qkvg(const float* __restrict__ qw, const float* __restrict__ kw,
                          const float* __restrict__ vw, const float* __restrict__ gw,
                          float* __restrict__ w) {
    int i = blockIdx.x * 256 + threadIdx.x;
    if (i < Dsz * Dsz) {
        int r = i >> 10, c = i & 1023;
        float* o = w + (size_t)r * 4096;
        o[c]        = tf32r(qw[i]);
        o[1024 + c] = tf32r(kw[i]);
        o[2048 + c] = tf32r(vw[i]);
        o[3072 + c] = tf32r(gw[i]);
    }
}
__global__ void cvt_all(const float* __restrict__ ow, float* __restrict__ dow,
                        const float* __restrict__ opw, float* __restrict__ dopw,
                        const float* __restrict__ s, float* __restrict__ dsr) {
    int i = blockIdx.x * 256 + threadIdx.x;
    if (i < Dsz * Dsz)   dow[i]  = tf32r(ow[i]);
    if (i < NDsz * Dsz)  dopw[i] = tf32r(opw[i]);
    if (i < Bsz * Lsz * NDsz) dsr[i] = tf32r(s[i]);
}

// ----------------------------- LayerNorm -----------------------------
__global__ void ln_kernel(const float* __restrict__ x, const float* __restrict__ g,
                          const float* __restrict__ b, float* __restrict__ y, int C, int rnd) {
    __shared__ float red[64];
    const int row = blockIdx.x;
    const float* xr = x + (size_t)row * C;
    float sum = 0.f, sq = 0.f;
    for (int i = threadIdx.x; i < C; i += 256) {
        float v = xr[i];
        sum += v; sq += v * v;
    }
    #pragma unroll
    for (int off = 16; off; off >>= 1) {
        sum += __shfl_xor_sync(0xffffffffu, sum, off);
        sq  += __shfl_xor_sync(0xffffffffu, sq,  off);
    }
    int w = threadIdx.x >> 5, lane = threadIdx.x & 31;
    if (lane == 0) { red[w] = sum; red[w + 32] = sq; }
    __syncthreads();
    if (w == 0) {
        float s1 = (lane < 8) ? red[lane] : 0.f;
        float s2 = (lane < 8) ? red[lane + 32] : 0.f;
        #pragma unroll
        for (int off = 4; off; off >>= 1) {
            s1 += __shfl_xor_sync(0xffffffffu, s1, off);
            s2 += __shfl_xor_sync(0xffffffffu, s2, off);
        }
        if (lane == 0) { red[0] = s1; red[1] = s2; }
    }
    __syncthreads();
    float mean = red[0] / (float)C;
    float var  = red[1] / (float)C - mean * mean;
    float inv  = rsqrtf(var + 1e-5f);
    float* yr = y + (size_t)row * C;
    for (int i = threadIdx.x; i < C; i += 256) {
        float v = (xr[i] - mean) * inv;
        if (g) v = v * g[i] + b[i];
        yr[i] = rnd ? tf32r(v) : v;
    }
}

// ----------------------------- tf32 GEMM 64x128x16, 256 threads (16x64 per warp) -------------
// EPI 0: C = A@B + bias
// EPI 1: C = sigmoid(A@B + bias)
// EPI 3: h2 = tf32r(sigmoid(even+bE)*aux + (odd+bO))     (interleaved; C,aux stride N/2)
// EPI 4: like 0 but rounds output for cols < 3*N/4 (q,k,v rounded; gate raw)
// EPI 5: C = (A@B + bias) * aux                          (final output gate multiply)
template<int EPI>
__global__ void __launch_bounds__(256)
gemm_tf32(const float* __restrict__ A, const float* __restrict__ B,
          const float* __restrict__ bias, float* __restrict__ C,
          const float* __restrict__ aux, int M, int N, int K) {
    __shared__ __align__(16) float As[2][64][20];
    __shared__ __align__(16) float Bs[2][16][136];
    const int tid  = threadIdx.x;
    const int wid  = tid >> 5, lane = tid & 31;
    const int g    = lane >> 2, t4 = lane & 3;
    const int wm   = (wid & 3) * 16;
    const int wn   = (wid >> 2) * 64;
    const int bx   = blockIdx.x, by = blockIdx.y;

    const int ar = tid >> 2, ac = (tid & 3) * 4;       // A: 1 float4/thread
    const int br = tid >> 4, bc = (tid & 15) * 8;      // B: 2 float4/thread
    const float* Ag = A + ((size_t)(by * 64 + ar)) * K + ac;
    const float* Bg = B + (size_t)br * N + bx * 128 + bc;

    float acc[8][4];
    #pragma unroll
    for (int nt = 0; nt < 8; nt++)
        #pragma unroll
        for (int c = 0; c < 4; c++) acc[nt][c] = 0.f;

    float4 ra, rb0, rb1;
    ra  = *(const float4*)(Ag);
    rb0 = *(const float4*)(Bg);
    rb1 = *(const float4*)(Bg + 4);

    *(float4*)&As[0][ar][ac]      = ra;
    *(float4*)&Bs[0][br][bc]      = rb0;
    *(float4*)&Bs[0][br][bc + 4]  = rb1;
    __syncthreads();

    const int nk = K >> 4;
    for (int it = 0; it < nk; it++) {
        const int buf = it & 1;
        if (it + 1 < nk) {
            ra  = *(const float4*)(Ag + (it + 1) * 16);
            const float* Bg2 = Bg + (size_t)(it + 1) * 16 * N;
            rb0 = *(const float4*)(Bg2);
            rb1 = *(const float4*)(Bg2 + 4);
        }
        #pragma unroll
        for (int ks = 0; ks < 2; ks++) {
            const int k0 = ks * 8;
            float a[4];
            a[0] = As[buf][wm + g][k0 + t4];
            a[1] = As[buf][wm + g + 8][k0 + t4];
            a[2] = As[buf][wm + g][k0 + t4 + 4];
            a[3] = As[buf][wm + g + 8][k0 + t4 + 4];
            #pragma unroll
            for (int nt = 0; nt < 8; nt++) {
                const float b0 = Bs[buf][k0 + t4][wn + nt * 8 + g];
                const float b1 = Bs[buf][k0 + t4 + 4][wn + nt * 8 + g];
                mma8(acc[nt], a, b0, b1);
            }
        }
        if (it + 1 < nk) {
            const int nb = buf ^ 1;
            *(float4*)&As[nb][ar][ac]     = ra;
            *(float4*)&Bs[nb][br][bc]     = rb0;
            *(float4*)&Bs[nb][br][bc + 4] = rb1;
        }
        __syncthreads();
    }

    #pragma unroll
    for (int nt = 0; nt < 8; nt++) {
        const int row0 = by * 64 + wm + g;
        const int col  = bx * 128 + wn + nt * 8 + 2 * t4;
        const float b0 = bias[col], b1 = bias[col + 1];
        if (EPI == 3) {
            const int f = col >> 1;
            const int ldc = N >> 1;
            float e0 = acc[nt][0] + b0, o0 = acc[nt][1] + b1;
            float e1 = acc[nt][2] + b0, o1 = acc[nt][3] + b1;
            C[(size_t)row0 * ldc + f]       = tf32r(sigmoidf_(e0) * aux[(size_t)row0 * ldc + f] + o0);
            C[(size_t)(row0 + 8) * ldc + f] = tf32r(sigmoidf_(e1) * aux[(size_t)(row0 + 8) * ldc + f] + o1);
        } else {
            float2 o0, o1;
            o0.x = acc[nt][0] + b0; o0.y = acc[nt][1] + b1;
            o1.x = acc[nt][2] + b0; o1.y = acc[nt][3] + b1;
            if (EPI == 1) {
                o0.x = sigmoidf_(o0.x); o0.y = sigmoidf_(o0.y);
                o1.x = sigmoidf_(o1.x); o1.y = sigmoidf_(o1.y);
            } else if (EPI == 5) {
                float2 x0 = *(const float2*)(aux + (size_t)row0 * N + col);
                float2 x1 = *(const float2*)(aux + (size_t)(row0 + 8) * N + col);
                o0.x *= x0.x; o0.y *= x0.y;
                o1.x *= x1.x; o1.y *= x1.y;
            } else if (EPI == 4) {
                if (col < (3 * N) / 4) {
                    o0.x = tf32r(o0.x); o0.y = tf32r(o0.y);
                    o1.x = tf32r(o1.x); o1.y = tf32r(o1.y);
                }
            }
            *(float2*)(C + (size_t)row0 * N + col)       = o0;
            *(float2*)(C + (size_t)(row0 + 8) * N + col) = o1;
        }
    }
}

// ----------------------------- V transpose: packed qkvg v-slice -> [B][D][L] ---------------------
__global__ void transpose_kernel(const float* __restrict__ src, float* __restrict__ dst) {
    __shared__ float tile[32][33];
    const int b = blockIdx.z;
    const int x0 = blockIdx.x * 32;
    const int y0 = blockIdx.y * 32;
    const int tx = threadIdx.x, ty = threadIdx.y;
    #pragma unroll
    for (int i = 0; i < 32; i += 8)
        tile[ty + i][tx] = src[((size_t)b * Lsz + y0 + ty + i) * 4096 + x0 + tx];
    __syncthreads();
    #pragma unroll
    for (int i = 0; i < 32; i += 8)
        dst[((size_t)b * Dsz + x0 + ty + i) * Lsz + y0 + tx] = tile[tx][ty + i];
}

// ----------------------------- pair bias via tensor cores -----------------------------
__global__ void __launch_bounds__(128)
pairbias_mma(const float* __restrict__ p, const float* __restrict__ eg,
             const float* __restrict__ eb, const float* __restrict__ ew,
             float* __restrict__ bias) {
    __shared__ __align__(16) float xs[128 * 68];
    __shared__ float sew[Esz * Hsz];
    __shared__ float seg[Esz], seb[Esz];
    const int tid = threadIdx.x, wid = tid >> 5, lane = tid & 31;
    const int g = lane >> 2, t4 = lane & 3;
    const int b = blockIdx.z, i = blockIdx.y, j0 = blockIdx.x * 128;

    float4 pr[16];
    const float4* prow = (const float4*)(p + (((size_t)b * Lsz + i) * Lsz + j0 + tid) * Esz);
    #pragma unroll
    for (int c = 0; c < 16; c++) pr[c] = prow[c];

    for (int t = tid; t < Esz * Hsz; t += 128) sew[t] = tf32r(ew[t]);
    if (tid < Esz) { seg[tid] = eg[tid]; seb[tid] = eb[tid]; }
    __syncthreads();

    float sum = 0.f, sq = 0.f;
    #pragma unroll
    for (int c = 0; c < 16; c++) {
        sum += pr[c].x + pr[c].y + pr[c].z + pr[c].w;
        sq  += pr[c].x * pr[c].x + pr[c].y * pr[c].y + pr[c].z * pr[c].z + pr[c].w * pr[c].w;
    }
    float mean = sum * (1.f / 64.f);
    float var  = sq * (1.f / 64.f) - mean * mean;
    float inv  = rsqrtf(var + 1e-5f);

    float* xrow = xs + tid * 68;
    #pragma unroll
    for (int c = 0; c < 16; c++) {
        float4 o;
        int e = c * 4;
        o.x = tf32r((pr[c].x - mean) * inv * seg[e + 0] + seb[e + 0]);
        o.y = tf32r((pr[c].y - mean) * inv * seg[e + 1] + seb[e + 1]);
        o.z = tf32r((pr[c].z - mean) * inv * seg[e + 2] + seb[e + 2]);
        o.w = tf32r((pr[c].w - mean) * inv * seg[e + 3] + seb[e + 3]);
        *(float4*)(xrow + e) = o;
    }
    __syncthreads();

    float acc[2][2][4];
    #pragma unroll
    for (int m = 0; m < 2; m++)
        #pragma unroll
        for (int n = 0; n < 2; n++)
            #pragma unroll
            for (int c = 0; c < 4; c++) acc[m][n][c] = 0.f;

    #pragma unroll
    for (int k = 0; k < 8; k++) {
        const int k0 = k * 8;
        float a[2][4];
        #pragma unroll
        for (int m = 0; m < 2; m++) {
            const int m0 = wid * 32 + m * 16;
            a[m][0] = xs[(m0 + g) * 68 + k0 + t4];
            a[m][1] = xs[(m0 + g + 8) * 68 + k0 + t4];
            a[m][2] = xs[(m0 + g) * 68 + k0 + t4 + 4];
            a[m][3] = xs[(m0 + g + 8) * 68 + k0 + t4 + 4];
        }
        #pragma unroll
        for (int n = 0; n < 2; n++) {
            const float b0 = sew[(k0 + t4) * 16 + n * 8 + g];
            const float b1 = sew[(k0 + t4 + 4) * 16 + n * 8 + g];
            mma8(acc[0][n], a[0], b0, b1);
            mma8(acc[1][n], a[1], b0, b1);
        }
    }

    const size_t LL = (size_t)Lsz * Lsz;
    #pragma unroll
    for (int m = 0; m < 2; m++) {
        const int jg = j0 + wid * 32 + m * 16 + g;
        #pragma unroll
        for (int n = 0; n < 2; n++) {
            const int h0 = n * 8 + 2 * t4;
            size_t base = ((size_t)(b * Hsz + h0) * Lsz + i) * Lsz;
            bias[base + jg]          = acc[m][n][0];
            bias[base + LL + jg]     = acc[m][n][1];
            bias[base + jg + 8]      = acc[m][n][2];
            bias[base + LL + jg + 8] = acc[m][n][3];
        }
    }
}

// ----------------------------- flash attention (row-major K/V, pre-rounded) ------------------
#define ATTN_SMEM ((2 * 64 * 68 + 128 * 68) * 4)
__global__ void __launch_bounds__(256)
attn_mma(const float* __restrict__ qkvg, const float* __restrict__ vt,
         const float* __restrict__ bias, float* __restrict__ y) {
    extern __shared__ __align__(16) float smx[];
    float* Ks = smx;                 // [64][68] K tile [j][d]
    float* Vs = smx + 64 * 68;       // [64][68] V^T tile [d][j]
    float* Ps = smx + 2 * 64 * 68;   // [128][68] Q staging, then P

    const int b = blockIdx.z, hh = blockIdx.y, i0 = blockIdx.x * 128;
    const int tid = threadIdx.x, wid = tid >> 5, lane = tid & 31;
    const int g = lane >> 2, t4 = lane & 3;
    const int wr0 = wid * 16;
    const int sr = tid >> 4, sc = (tid & 15) * 4;

    for (int rr = sr; rr < 128; rr += 16) {
        float4 v = *(const float4*)(qkvg + ((size_t)(b * Lsz) + i0 + rr) * 4096 + hh * 64 + sc);
        float* d = Ps + rr * 68 + sc;
        d[0] = v.x * QSCALE; d[1] = v.y * QSCALE;
        d[2] = v.z * QSCALE; d[3] = v.w * QSCALE;
    }
    __syncthreads();

    float qa[8][4];
    #pragma unroll
    for (int kt = 0; kt < 8; kt++) {
        const int k0 = kt * 8;
        qa[kt][0] = Ps[(wr0 + g) * 68 + k0 + t4];
        qa[kt][1] = Ps[(wr0 + g + 8) * 68 + k0 + t4];
        qa[kt][2] = Ps[(wr0 + g) * 68 + k0 + t4 + 4];
        qa[kt][3] = Ps[(wr0 + g + 8) * 68 + k0 + t4 + 4];
    }
    float oacc[8][4];
    #pragma unroll
    for (int nt = 0; nt < 8; nt++)
        #pragma unroll
        for (int c = 0; c < 4; c++) oacc[nt][c] = 0.f;
    float m0 = -1e30f, m1 = -1e30f, l0 = 0.f, l1 = 0.f;
    __syncthreads();

    const float* brow0 = bias + (((size_t)(b * Hsz + hh)) * Lsz + i0 + wr0 + g) * Lsz;
    const float* brow1 = brow0 + (size_t)8 * Lsz;

    for (int jb = 0; jb < Lsz; jb += 64) {
        for (int rr = sr; rr < 64; rr += 16) {
            float4 kv = *(const float4*)(qkvg + ((size_t)(b * Lsz) + jb + rr) * 4096 + 1024 + hh * 64 + sc);
            *(float4*)(Ks + rr * 68 + sc) = kv;
            float4 vv = *(const float4*)(vt + ((size_t)(b * Dsz) + hh * 64 + rr) * Lsz + jb + sc);
            *(float4*)(Vs + rr * 68 + sc) = vv;
        }
        __syncthreads();

        float sacc[8][4];
        #pragma unroll
        for (int nt = 0; nt < 8; nt++) {
            float2 bb0 = *(const float2*)(brow0 + jb + nt * 8 + 2 * t4);
            float2 bb1 = *(const float2*)(brow1 + jb + nt * 8 + 2 * t4);
            sacc[nt][0] = bb0.x; sacc[nt][1] = bb0.y;
            sacc[nt][2] = bb1.x; sacc[nt][3] = bb1.y;
        }
        #pragma unroll
        for (int kt = 0; kt < 8; kt++) {
            const int k0 = kt * 8;
            #pragma unroll
            for (int nt = 0; nt < 8; nt++) {
                const float b0 = Ks[(nt * 8 + g) * 68 + k0 + t4];
                const float b1 = Ks[(nt * 8 + g) * 68 + k0 + t4 + 4];
                mma8(sacc[nt], qa[kt], b0, b1);
            }
        }
        float mx0 = -1e30f, mx1 = -1e30f;
        #pragma unroll
        for (int nt = 0; nt < 8; nt++) {
            mx0 = fmaxf(mx0, fmaxf(sacc[nt][0], sacc[nt][1]));
            mx1 = fmaxf(mx1, fmaxf(sacc[nt][2], sacc[nt][3]));
        }
        mx0 = fmaxf(mx0, __shfl_xor_sync(0xffffffffu, mx0, 1));
        mx0 = fmaxf(mx0, __shfl_xor_sync(0xffffffffu, mx0, 2));
        mx1 = fmaxf(mx1, __shfl_xor_sync(0xffffffffu, mx1, 1));
        mx1 = fmaxf(mx1, __shfl_xor_sync(0xffffffffu, mx1, 2));
        const float nm0 = fmaxf(m0, mx0), nm1 = fmaxf(m1, mx1);
        const float c0 = fexp(m0 - nm0), c1 = fexp(m1 - nm1);
        m0 = nm0; m1 = nm1;
        float rs0 = 0.f, rs1 = 0.f;
        #pragma unroll
        for (int nt = 0; nt < 8; nt++) {
            float p0 = fexp(sacc[nt][0] - nm0);
            float p1 = fexp(sacc[nt][1] - nm0);
            float p2 = fexp(sacc[nt][2] - nm1);
            float p3 = fexp(sacc[nt][3] - nm1);
            rs0 += p0 + p1; rs1 += p2 + p3;
            float* pr0 = Ps + (wr0 + g) * 68 + nt * 8 + 2 * t4;
            pr0[0] = tf32r(p0); pr0[1] = tf32r(p1);
            float* pr1 = Ps + (wr0 + g + 8) * 68 + nt * 8 + 2 * t4;
            pr1[0] = tf32r(p2); pr1[1] = tf32r(p3);
            oacc[nt][0] *= c0; oacc[nt][1] *= c0;
            oacc[nt][2] *= c1; oacc[nt][3] *= c1;
        }
        rs0 += __shfl_xor_sync(0xffffffffu, rs0, 1);
        rs0 += __shfl_xor_sync(0xffffffffu, rs0, 2);
        rs1 += __shfl_xor_sync(0xffffffffu, rs1, 1);
        rs1 += __shfl_xor_sync(0xffffffffu, rs1, 2);
        l0 = l0 * c0 + rs0;
        l1 = l1 * c1 + rs1;
        __syncwarp();

        #pragma unroll
        for (int kt = 0; kt < 8; kt++) {
            const int k0 = kt * 8;
            float pa[4];
            pa[0] = Ps[(wr0 + g) * 68 + k0 + t4];
            pa[1] = Ps[(wr0 + g + 8) * 68 + k0 + t4];
            pa[2] = Ps[(wr0 + g) * 68 + k0 + t4 + 4];
            pa[3] = Ps[(wr0 + g + 8) * 68 + k0 + t4 + 4];
            #pragma unroll
            for (int nt = 0; nt < 8; nt++) {
                const float b0 = Vs[(nt * 8 + g) * 68 + k0 + t4];
                const float b1 = Vs[(nt * 8 + g) * 68 + k0 + t4 + 4];
                mma8(oacc[nt], pa, b0, b1);
            }
        }
        __syncthreads();
    }

    const float inv0 = __fdividef(1.f, l0), inv1 = __fdividef(1.f, l1);
    #pragma unroll
    for (int nt = 0; nt < 8; nt++) {
        const int col = hh * 64 + nt * 8 + 2 * t4;
        size_t gr0 = ((size_t)(b * Lsz) + i0 + wr0 + g) * 4096 + 3072 + col;
        size_t gr1 = gr0 + (size_t)8 * 4096;
        float2 gv0 = *(const float2*)(qkvg + gr0);
        float2 gv1 = *(const float2*)(qkvg + gr1);
        size_t r0 = ((size_t)(b * Lsz) + i0 + wr0 + g) * Dsz + col;
        size_t r1 = r0 + (size_t)8 * Dsz;
        float2 o0, o1;
        o0.x = tf32r(oacc[nt][0] * inv0 * sigmoidf_(gv0.x));
        o0.y = tf32r(oacc[nt][1] * inv0 * sigmoidf_(gv0.y));
        o1.x = tf32r(oacc[nt][2] * inv1 * sigmoidf_(gv1.x));
        o1.y = tf32r(oacc[nt][3] * inv1 * sigmoidf_(gv1.y));
        *(float2*)(y + r0) = o0;
        *(float2*)(y + r1) = o1;
    }
}

// ----------------------------- launch -----------------------------
static cudaStream_t s_stream2 = nullptr;
static cudaEvent_t  s_evFork = nullptr, s_evJoin = nullptr;

extern "C" void kernel_launch(void* const* d_in, const int* in_sizes, int n_in,
                              void* d_out, int out_size) {
    const float* h     = (const float*)d_in[0];
    const float* p     = (const float*)d_in[1];
    const float* s     = (const float*)d_in[2];
    const float* sln_g = (const float*)d_in[3];
    const float* sln_b = (const float*)d_in[4];
    const float* s1_w  = (const float*)d_in[5];
    const float* s1_b  = (const float*)d_in[6];
    const float* s2_w  = (const float*)d_in[7];
    const float* s2_b  = (const float*)d_in[8];
    const float* q_w   = (const float*)d_in[9];
    const float* q_b   = (const float*)d_in[10];
    const float* k_w   = (const float*)d_in[11];
    const float* k_b   = (const float*)d_in[12];
    const float* v_w   = (const float*)d_in[13];
    const float* v_b   = (const float*)d_in[14];
    const float* eln_g = (const float*)d_in[15];
    const float* eln_b = (const float*)d_in[16];
    const float* e_w   = (const float*)d_in[17];
    const float* gw    = (const float*)d_in[18];
    const float* gb    = (const float*)d_in[19];
    const float* o_w   = (const float*)d_in[20];
    const float* o_b   = (const float*)d_in[21];
    const float* op_w  = (const float*)d_in[22];
    const float* op_b  = (const float*)d_in[23];
    float* out = (float*)d_out;

    float *hn, *sn, *h2, *qkvg, *vtp, *yp, *gatep, *biasp;
    float *wqkvg, *bqkvg, *ws12i, *bs12i, *wo, *wop, *sr;
    cudaGetSymbolAddress((void**)&hn,    g_hn);
    cudaGetSymbolAddress((void**)&sn,    g_sn);
    cudaGetSymbolAddress((void**)&h2,    g_h2);
    cudaGetSymbolAddress((void**)&qkvg,  g_qkvg);
    cudaGetSymbolAddress((void**)&vtp,   g_vt);
    cudaGetSymbolAddress((void**)&yp,    g_yb);
    cudaGetSymbolAddress((void**)&gatep, g_gate);
    cudaGetSymbolAddress((void**)&biasp, g_bias);
    cudaGetSymbolAddress((void**)&wqkvg, g_wqkvg);
    cudaGetSymbolAddress((void**)&bqkvg, g_bqkvg);
    cudaGetSymbolAddress((void**)&ws12i, g_ws12i);
    cudaGetSymbolAddress((void**)&bs12i, g_bs12i);
    cudaGetSymbolAddress((void**)&wo,    g_wo);
    cudaGetSymbolAddress((void**)&wop,   g_wop);
    cudaGetSymbolAddress((void**)&sr,    g_sr);

    if (!s_stream2) {
        cudaStreamCreateWithFlags(&s_stream2, cudaStreamNonBlocking);
        cudaEventCreateWithFlags(&s_evFork, cudaEventDisableTiming);
        cudaEventCreateWithFlags(&s_evJoin, cudaEventDisableTiming);
        cudaFuncSetAttribute(attn_mma, cudaFuncAttributeMaxDynamicSharedMemorySize, ATTN_SMEM);
    }

    const int M = Bsz * Lsz;           // 2048

    // ---- fork: stream B runs pairbias (tensor-core version) alone ----
    cudaEventRecord(s_evFork, 0);
    cudaStreamWaitEvent(s_stream2, s_evFork, 0);
    pairbias_mma<<<dim3(Lsz / 128, Lsz, Bsz), 128, 0, s_stream2>>>(p, eln_g, eln_b, e_w, biasp);
    cudaEventRecord(s_evJoin, s_stream2);

    // ---- stream A (default): everything else ----
    pack_s12<<<(NDsz * Dsz + 255) / 256, 256>>>(s1_w, s2_w, s1_b, s2_b, ws12i, bs12i);
    pack_qkvg<<<(Dsz * Dsz + 255) / 256, 256>>>(q_w, k_w, v_w, gw, wqkvg);
    cvt_all<<<(Dsz * Dsz + 255) / 256, 256>>>(o_w, wo, op_w, wop, s, sr);
    const float* bsrc[4] = {q_b, k_b, v_b, gb};
    for (int j = 0; j < 4; j++)
        cudaMemcpyAsync(bqkvg + j * 1024, bsrc[j], 1024 * 4, cudaMemcpyDeviceToDevice, 0);

    ln_kernel<<<M, 256>>>(h, nullptr, nullptr, hn, Dsz, 0);
    ln_kernel<<<M, 256>>>(s, sln_g, sln_b, sn, NDsz, 1);

    gemm_tf32<3><<<dim3(2048 / 128, M / 64), 256>>>(sn, ws12i, bs12i, h2, hn, M, 2048, NDsz);
    gemm_tf32<4><<<dim3(4096 / 128, M / 64), 256>>>(h2, wqkvg, bqkvg, qkvg, nullptr, M, 4096, Dsz);
    transpose_kernel<<<dim3(32, 32, Bsz), dim3(32, 8)>>>(qkvg + 2048, vtp);
    gemm_tf32<1><<<dim3(Dsz / 128, M / 64), 256>>>(sr, wop, op_b, gatep, nullptr, M, Dsz, NDsz);

    // ---- join: attention needs pairbias ----
    cudaStreamWaitEvent(0, s_evJoin, 0);

    attn_mma<<<dim3(Lsz / 128, Hsz, Bsz), 256, ATTN_SMEM>>>(qkvg, vtp, biasp, yp);

    // o-projection with fused final gate multiply -> out
    gemm_tf32<5><<<dim3(Dsz / 128, M / 64), 256>>>(yp, wo, o_b, out, gatep, M, Dsz, Dsz);
}

// round 14
// speedup vs baseline: 1.1261x; 1.1261x over previous
#include <cuda_runtime.h>
#include <math.h>
#include <stdint.h>

#define Bsz 2
#define Lsz 1024
#define Dsz 1024
#define Hsz 16
#define Esz 64
#define NDsz 512
#define HDsz 64
#define QSCALE 0.125f   // 1/sqrt(64), exact power of two

// ----------------------------- scratch (device globals, no allocs) -----------------------------
__device__ float g_hn   [Bsz*Lsz*Dsz];
__device__ float g_sn   [Bsz*Lsz*NDsz];
__device__ float g_h2   [Bsz*Lsz*Dsz];
__device__ float g_qkvg [(size_t)Bsz*Lsz*4*Dsz];   // [2048][4096]: q|k|v|graw
__device__ float g_vt   [Bsz*Lsz*Dsz];             // V^T [B][D][L]
__device__ float g_yb   [Bsz*Lsz*Dsz];
__device__ float g_gate [Bsz*Lsz*Dsz];             // sigmoid(s@op_w+op_b)
__device__ float g_bias [(size_t)Bsz*Hsz*Lsz*Lsz]; // 128 MB, [b][h][i][j]
__device__ float g_wqkvg[Dsz*4*Dsz];               // [1024][4096] tf32-rounded
__device__ float g_bqkvg[4*Dsz];
__device__ float g_ws12i[NDsz*2*Dsz];              // [512][2048] interleaved, rounded
__device__ float g_bs12i[2*Dsz];
__device__ float g_wo   [Dsz*Dsz];                 // o_w rounded
__device__ float g_wop  [NDsz*Dsz];                // op_w rounded
__device__ float g_sr   [Bsz*Lsz*NDsz];            // s rounded

// ----------------------------- fast math -----------------------------
__device__ __forceinline__ float fexp(float x) {
    x = fminf(fmaxf(x, -80.f), 80.f);
    float t  = x * 1.44269504f;
    float fj = t + 12582912.f;
    int   i  = __float_as_int(fj) - 0x4B400000;
    float j  = fj - 12582912.f;
    float f  = t - j;
    float u  = f * 0.69314718f;
    float p  = 1.f + u * (1.f + u * (0.5f + u * (0.166666667f +
               u * (0.0416666667f + u * 0.00833333333f))));
    return p * __int_as_float((i + 127) << 23);
}
__device__ __forceinline__ float sigmoidf_(float x) {
    return __fdividef(1.0f, 1.0f + fexp(-x));
}
__device__ __forceinline__ float tf32r(float x) {
    uint32_t u;
    asm("cvt.rna.tf32.f32 %0, %1;" : "=r"(u) : "f"(x));
    return __uint_as_float(u);
}
__device__ __forceinline__ void mma8(float* d, const float* a, float b0f, float b1f) {
    const uint32_t* A = (const uint32_t*)a;
    uint32_t B0 = __float_as_uint(b0f), B1 = __float_as_uint(b1f);
    asm volatile(
        "mma.sync.aligned.m16n8k8.row.col.f32.tf32.tf32.f32 "
        "{%0,%1,%2,%3}, {%4,%5,%6,%7}, {%8,%9}, {%0,%1,%2,%3};\n"
        : "+f"(d[0]), "+f"(d[1]), "+f"(d[2]), "+f"(d[3])
        : "r"(A[0]), "r"(A[1]), "r"(A[2]), "r"(A[3]), "r"(B0), "r"(B1));
}

// ----------------------------- pack / convert kernels -----------------------------
__global__ void pack_s12(const float* __restrict__ s1w, const float* __restrict__ s2w,
                         const float* __restrict__ s1b, const float* __restrict__ s2b,
                         float* __restrict__ wi, float* __restrict__ bi) {
    int i = blockIdx.x * 256 + threadIdx.x;
    if (i < NDsz * Dsz) {
        int k = i >> 10, f = i & 1023;
        float2 v; v.x = tf32r(s1w[i]); v.y = tf32r(s2w[i]);
        *(float2*)(wi + (size_t)k * 2048 + 2 * f) = v;
    }
    if (i < Dsz) { bi[2 * i] = s1b[i]; bi[2 * i + 1] = s2b[i]; }
}
__global__ void pack_qkvg(const float* __restrict__ qw, const float* __restrict__ kw,
                          const float* __restrict__ vw, const float* __restrict__ gw,
                          float* __restrict__ w) {
    int i = blockIdx.x * 256 + threadIdx.x;
    if (i < Dsz * Dsz) {
        int r = i >> 10, c = i & 1023;
        float* o = w + (size_t)r * 4096;
        o[c]        = tf32r(qw[i]);
        o[1024 + c] = tf32r(kw[i]);
        o[2048 + c] = tf32r(vw[i]);
        o[3072 + c] = tf32r(gw[i]);
    }
}
__global__ void cvt_all(const float* __restrict__ ow, float* __restrict__ dow,
                        const float* __restrict__ opw, float* __restrict__ dopw,
                        const float* __restrict__ s, float* __restrict__ dsr) {
    int i = blockIdx.x * 256 + threadIdx.x;
    if (i < Dsz * Dsz)   dow[i]  = tf32r(ow[i]);
    if (i < NDsz * Dsz)  dopw[i] = tf32r(opw[i]);
    if (i < Bsz * Lsz * NDsz) dsr[i] = tf32r(s[i]);
}

// ----------------------------- LayerNorm -----------------------------
__global__ void ln_kernel(const float* __restrict__ x, const float* __restrict__ g,
                          const float* __restrict__ b, float* __restrict__ y, int C, int rnd) {
    __shared__ float red[64];
    const int row = blockIdx.x;
    const float* xr = x + (size_t)row * C;
    float sum = 0.f, sq = 0.f;
    for (int i = threadIdx.x; i < C; i += 256) {
        float v = xr[i];
        sum += v; sq += v * v;
    }
    #pragma unroll
    for (int off = 16; off; off >>= 1) {
        sum += __shfl_xor_sync(0xffffffffu, sum, off);
        sq  += __shfl_xor_sync(0xffffffffu, sq,  off);
    }
    int w = threadIdx.x >> 5, lane = threadIdx.x & 31;
    if (lane == 0) { red[w] = sum; red[w + 32] = sq; }
    __syncthreads();
    if (w == 0) {
        float s1 = (lane < 8) ? red[lane] : 0.f;
        float s2 = (lane < 8) ? red[lane + 32] : 0.f;
        #pragma unroll
        for (int off = 4; off; off >>= 1) {
            s1 += __shfl_xor_sync(0xffffffffu, s1, off);
            s2 += __shfl_xor_sync(0xffffffffu, s2, off);
        }
        if (lane == 0) { red[0] = s1; red[1] = s2; }
    }
    __syncthreads();
    float mean = red[0] / (float)C;
    float var  = red[1] / (float)C - mean * mean;
    float inv  = rsqrtf(var + 1e-5f);
    float* yr = y + (size_t)row * C;
    for (int i = threadIdx.x; i < C; i += 256) {
        float v = (xr[i] - mean) * inv;
        if (g) v = v * g[i] + b[i];
        yr[i] = rnd ? tf32r(v) : v;
    }
}

// ----------------------------- tf32 GEMM 64x128x16, 128 threads (round-11 proven) ------------
// EPI 0: C = A@B + bias
// EPI 1: C = sigmoid(A@B + bias)
// EPI 3: h2 = tf32r(sigmoid(even+bE)*aux + (odd+bO))     (interleaved; C,aux stride N/2)
// EPI 4: like 0 but rounds output for cols < 3*N/4 (q,k,v rounded; gate raw)
// EPI 5: C = (A@B + bias) * aux                          (final output gate multiply)
template<int EPI>
__global__ void __launch_bounds__(128)
gemm_tf32(const float* __restrict__ A, const float* __restrict__ B,
          const float* __restrict__ bias, float* __restrict__ C,
          const float* __restrict__ aux, int M, int N, int K) {
    __shared__ __align__(16) float As[2][64][20];
    __shared__ __align__(16) float Bs[2][16][136];
    const int tid  = threadIdx.x;
    const int wid  = tid >> 5, lane = tid & 31;
    const int g    = lane >> 2, t4 = lane & 3;
    const int wm   = (wid & 1) * 32;
    const int wn   = (wid >> 1) * 64;
    const int bx   = blockIdx.x, by = blockIdx.y;

    const int ar = tid >> 2, ac = (tid & 3) * 4;
    const int br = tid >> 5, bc = (tid & 31) * 4;
    const float* Ag = A + ((size_t)(by * 64 + ar)) * K + ac;
    const float* Bg = B + (size_t)br * N + bx * 128 + bc;

    float acc[2][8][4];
    #pragma unroll
    for (int mt = 0; mt < 2; mt++)
        #pragma unroll
        for (int nt = 0; nt < 8; nt++)
            #pragma unroll
            for (int c = 0; c < 4; c++) acc[mt][nt][c] = 0.f;

    float4 ra0, ra1, rb[4];
    ra0 = *(const float4*)(Ag);
    ra1 = *(const float4*)(Ag + (size_t)32 * K);
    #pragma unroll
    for (int i = 0; i < 4; i++)
        rb[i] = *(const float4*)(Bg + (size_t)(4 * i) * N);

    *(float4*)&As[0][ar][ac]      = ra0;
    *(float4*)&As[0][ar + 32][ac] = ra1;
    #pragma unroll
    for (int i = 0; i < 4; i++)
        *(float4*)&Bs[0][br + 4 * i][bc] = rb[i];
    __syncthreads();

    const int nk = K >> 4;
    for (int it = 0; it < nk; it++) {
        const int buf = it & 1;
        if (it + 1 < nk) {
            const float* Ag2 = Ag + (it + 1) * 16;
            ra0 = *(const float4*)(Ag2);
            ra1 = *(const float4*)(Ag2 + (size_t)32 * K);
            const float* Bg2 = Bg + (size_t)(it + 1) * 16 * N;
            #pragma unroll
            for (int i = 0; i < 4; i++)
                rb[i] = *(const float4*)(Bg2 + (size_t)(4 * i) * N);
        }
        #pragma unroll
        for (int ks = 0; ks < 2; ks++) {
            const int k0 = ks * 8;
            float a[2][4];
            #pragma unroll
            for (int mt = 0; mt < 2; mt++) {
                const int m0 = wm + mt * 16;
                a[mt][0] = As[buf][m0 + g][k0 + t4];
                a[mt][1] = As[buf][m0 + g + 8][k0 + t4];
                a[mt][2] = As[buf][m0 + g][k0 + t4 + 4];
                a[mt][3] = As[buf][m0 + g + 8][k0 + t4 + 4];
            }
            #pragma unroll
            for (int nt = 0; nt < 8; nt++) {
                const float b0 = Bs[buf][k0 + t4][wn + nt * 8 + g];
                const float b1 = Bs[buf][k0 + t4 + 4][wn + nt * 8 + g];
                mma8(acc[0][nt], a[0], b0, b1);
                mma8(acc[1][nt], a[1], b0, b1);
            }
        }
        if (it + 1 < nk) {
            const int nb = buf ^ 1;
            *(float4*)&As[nb][ar][ac]      = ra0;
            *(float4*)&As[nb][ar + 32][ac] = ra1;
            #pragma unroll
            for (int i = 0; i < 4; i++)
                *(float4*)&Bs[nb][br + 4 * i][bc] = rb[i];
        }
        __syncthreads();
    }

    #pragma unroll
    for (int mt = 0; mt < 2; mt++) {
        #pragma unroll
        for (int nt = 0; nt < 8; nt++) {
            const int row0 = by * 64 + wm + mt * 16 + g;
            const int col  = bx * 128 + wn + nt * 8 + 2 * t4;
            const float b0 = bias[col], b1 = bias[col + 1];
            if (EPI == 3) {
                const int f = col >> 1;
                const int ldc = N >> 1;
                float e0 = acc[mt][nt][0] + b0, o0 = acc[mt][nt][1] + b1;
                float e1 = acc[mt][nt][2] + b0, o1 = acc[mt][nt][3] + b1;
                C[(size_t)row0 * ldc + f]       = tf32r(sigmoidf_(e0) * aux[(size_t)row0 * ldc + f] + o0);
                C[(size_t)(row0 + 8) * ldc + f] = tf32r(sigmoidf_(e1) * aux[(size_t)(row0 + 8) * ldc + f] + o1);
            } else {
                float2 o0, o1;
                o0.x = acc[mt][nt][0] + b0; o0.y = acc[mt][nt][1] + b1;
                o1.x = acc[mt][nt][2] + b0; o1.y = acc[mt][nt][3] + b1;
                if (EPI == 1) {
                    o0.x = sigmoidf_(o0.x); o0.y = sigmoidf_(o0.y);
                    o1.x = sigmoidf_(o1.x); o1.y = sigmoidf_(o1.y);
                } else if (EPI == 5) {
                    float2 x0 = *(const float2*)(aux + (size_t)row0 * N + col);
                    float2 x1 = *(const float2*)(aux + (size_t)(row0 + 8) * N + col);
                    o0.x *= x0.x; o0.y *= x0.y;
                    o1.x *= x1.x; o1.y *= x1.y;
                } else if (EPI == 4) {
                    if (col < (3 * N) / 4) {
                        o0.x = tf32r(o0.x); o0.y = tf32r(o0.y);
                        o1.x = tf32r(o1.x); o1.y = tf32r(o1.y);
                    }
                }
                *(float2*)(C + (size_t)row0 * N + col)       = o0;
                *(float2*)(C + (size_t)(row0 + 8) * N + col) = o1;
            }
        }
    }
}

// ----------------------------- V transpose: packed qkvg v-slice -> [B][D][L] ---------------------
__global__ void transpose_kernel(const float* __restrict__ src, float* __restrict__ dst) {
    __shared__ float tile[32][33];
    const int b = blockIdx.z;
    const int x0 = blockIdx.x * 32;
    const int y0 = blockIdx.y * 32;
    const int tx = threadIdx.x, ty = threadIdx.y;
    #pragma unroll
    for (int i = 0; i < 32; i += 8)
        tile[ty + i][tx] = src[((size_t)b * Lsz + y0 + ty + i) * 4096 + x0 + tx];
    __syncthreads();
    #pragma unroll
    for (int i = 0; i < 32; i += 8)
        dst[((size_t)b * Dsz + x0 + ty + i) * Lsz + y0 + tx] = tile[tx][ty + i];
}

// ----------------------------- pair bias via tensor cores -----------------------------
__global__ void __launch_bounds__(128)
pairbias_mma(const float* __restrict__ p, const float* __restrict__ eg,
             const float* __restrict__ eb, const float* __restrict__ ew,
             float* __restrict__ bias) {
    __shared__ __align__(16) float xs[128 * 68];
    __shared__ float sew[Esz * Hsz];
    __shared__ float seg[Esz], seb[Esz];
    const int tid = threadIdx.x, wid = tid >> 5, lane = tid & 31;
    const int g = lane >> 2, t4 = lane & 3;
    const int b = blockIdx.z, i = blockIdx.y, j0 = blockIdx.x * 128;

    float4 pr[16];
    const float4* prow = (const float4*)(p + (((size_t)b * Lsz + i) * Lsz + j0 + tid) * Esz);
    #pragma unroll
    for (int c = 0; c < 16; c++) pr[c] = prow[c];

    for (int t = tid; t < Esz * Hsz; t += 128) sew[t] = tf32r(ew[t]);
    if (tid < Esz) { seg[tid] = eg[tid]; seb[tid] = eb[tid]; }
    __syncthreads();

    float sum = 0.f, sq = 0.f;
    #pragma unroll
    for (int c = 0; c < 16; c++) {
        sum += pr[c].x + pr[c].y + pr[c].z + pr[c].w;
        sq  += pr[c].x * pr[c].x + pr[c].y * pr[c].y + pr[c].z * pr[c].z + pr[c].w * pr[c].w;
    }
    float mean = sum * (1.f / 64.f);
    float var  = sq * (1.f / 64.f) - mean * mean;
    float inv  = rsqrtf(var + 1e-5f);

    float* xrow = xs + tid * 68;
    #pragma unroll
    for (int c = 0; c < 16; c++) {
        float4 o;
        int e = c * 4;
        o.x = tf32r((pr[c].x - mean) * inv * seg[e + 0] + seb[e + 0]);
        o.y = tf32r((pr[c].y - mean) * inv * seg[e + 1] + seb[e + 1]);
        o.z = tf32r((pr[c].z - mean) * inv * seg[e + 2] + seb[e + 2]);
        o.w = tf32r((pr[c].w - mean) * inv * seg[e + 3] + seb[e + 3]);
        *(float4*)(xrow + e) = o;
    }
    __syncthreads();

    float acc[2][2][4];
    #pragma unroll
    for (int m = 0; m < 2; m++)
        #pragma unroll
        for (int n = 0; n < 2; n++)
            #pragma unroll
            for (int c = 0; c < 4; c++) acc[m][n][c] = 0.f;

    #pragma unroll
    for (int k = 0; k < 8; k++) {
        const int k0 = k * 8;
        float a[2][4];
        #pragma unroll
        for (int m = 0; m < 2; m++) {
            const int m0 = wid * 32 + m * 16;
            a[m][0] = xs[(m0 + g) * 68 + k0 + t4];
            a[m][1] = xs[(m0 + g + 8) * 68 + k0 + t4];
            a[m][2] = xs[(m0 + g) * 68 + k0 + t4 + 4];
            a[m][3] = xs[(m0 + g + 8) * 68 + k0 + t4 + 4];
        }
        #pragma unroll
        for (int n = 0; n < 2; n++) {
            const float b0 = sew[(k0 + t4) * 16 + n * 8 + g];
            const float b1 = sew[(k0 + t4 + 4) * 16 + n * 8 + g];
            mma8(acc[0][n], a[0], b0, b1);
            mma8(acc[1][n], a[1], b0, b1);
        }
    }

    const size_t LL = (size_t)Lsz * Lsz;
    #pragma unroll
    for (int m = 0; m < 2; m++) {
        const int jg = j0 + wid * 32 + m * 16 + g;
        #pragma unroll
        for (int n = 0; n < 2; n++) {
            const int h0 = n * 8 + 2 * t4;
            size_t base = ((size_t)(b * Hsz + h0) * Lsz + i) * Lsz;
            bias[base + jg]          = acc[m][n][0];
            bias[base + LL + jg]     = acc[m][n][1];
            bias[base + jg + 8]      = acc[m][n][2];
            bias[base + LL + jg + 8] = acc[m][n][3];
        }
    }
}

// ----------------------------- flash attention (double-buffered K/V, 1 sync/tile) ------------
#define ATTN_SMEM ((4 * 4352 + 128 * 68) * 4)   // K[2]+V[2] + Ps = 104448 B
__global__ void __launch_bounds__(256)
attn_mma(const float* __restrict__ qkvg, const float* __restrict__ vt,
         const float* __restrict__ bias, float* __restrict__ y) {
    extern __shared__ __align__(16) float smx[];
    // K buffers: smx[0..8704), V buffers: smx[8704..17408), Ps: smx[17408..)
    float* Ps = smx + 17408;   // [128][68] Q staging, then P

    const int b = blockIdx.z, hh = blockIdx.y, i0 = blockIdx.x * 128;
    const int tid = threadIdx.x, wid = tid >> 5, lane = tid & 31;
    const int g = lane >> 2, t4 = lane & 3;
    const int wr0 = wid * 16;
    const int sr = tid >> 4, sc = (tid & 15) * 4;

    for (int rr = sr; rr < 128; rr += 16) {
        float4 v = *(const float4*)(qkvg + ((size_t)(b * Lsz) + i0 + rr) * 4096 + hh * 64 + sc);
        float* d = Ps + rr * 68 + sc;
        d[0] = v.x * QSCALE; d[1] = v.y * QSCALE;
        d[2] = v.z * QSCALE; d[3] = v.w * QSCALE;
    }
    __syncthreads();

    float qa[8][4];
    #pragma unroll
    for (int kt = 0; kt < 8; kt++) {
        const int k0 = kt * 8;
        qa[kt][0] = Ps[(wr0 + g) * 68 + k0 + t4];
        qa[kt][1] = Ps[(wr0 + g + 8) * 68 + k0 + t4];
        qa[kt][2] = Ps[(wr0 + g) * 68 + k0 + t4 + 4];
        qa[kt][3] = Ps[(wr0 + g + 8) * 68 + k0 + t4 + 4];
    }
    float oacc[8][4];
    #pragma unroll
    for (int nt = 0; nt < 8; nt++)
        #pragma unroll
        for (int c = 0; c < 4; c++) oacc[nt][c] = 0.f;
    float m0 = -1e30f, m1 = -1e30f, l0 = 0.f, l1 = 0.f;
    __syncthreads();

    const float* brow0 = bias + (((size_t)(b * Hsz + hh)) * Lsz + i0 + wr0 + g) * Lsz;
    const float* brow1 = brow0 + (size_t)8 * Lsz;
    const float* kbase = qkvg + (size_t)(b * Lsz) * 4096 + 1024 + hh * 64;
    const float* vbase = vt + ((size_t)(b * Dsz) + hh * 64) * Lsz;

    // stage tile 0 into buffer 0
    for (int rr = sr; rr < 64; rr += 16) {
        float4 kv = *(const float4*)(kbase + (size_t)rr * 4096 + sc);
        *(float4*)(smx + rr * 68 + sc) = kv;
        float4 vv = *(const float4*)(vbase + (size_t)rr * Lsz + sc);
        *(float4*)(smx + 8704 + rr * 68 + sc) = vv;
    }
    __syncthreads();

    for (int jt = 0; jt < 16; jt++) {
        const int jb = jt * 64;
        const int buf = jt & 1;
        float* Ks = smx + buf * 4352;
        float* Vs = smx + 8704 + buf * 4352;

        // issue next tile's copy into the free buffer (drains under compute)
        if (jt + 1 < 16) {
            float* Kn = smx + (buf ^ 1) * 4352;
            float* Vn = smx + 8704 + (buf ^ 1) * 4352;
            const int jn = jb + 64;
            for (int rr = sr; rr < 64; rr += 16) {
                float4 kv = *(const float4*)(kbase + (size_t)(jn + rr) * 4096 + sc);
                *(float4*)(Kn + rr * 68 + sc) = kv;
                float4 vv = *(const float4*)(vbase + (size_t)rr * Lsz + jn + sc);
                *(float4*)(Vn + rr * 68 + sc) = vv;
            }
        }

        // S = Q K^T + bias
        float sacc[8][4];
        #pragma unroll
        for (int nt = 0; nt < 8; nt++) {
            float2 bb0 = *(const float2*)(brow0 + jb + nt * 8 + 2 * t4);
            float2 bb1 = *(const float2*)(brow1 + jb + nt * 8 + 2 * t4);
            sacc[nt][0] = bb0.x; sacc[nt][1] = bb0.y;
            sacc[nt][2] = bb1.x; sacc[nt][3] = bb1.y;
        }
        #pragma unroll
        for (int kt = 0; kt < 8; kt++) {
            const int k0 = kt * 8;
            #pragma unroll
            for (int nt = 0; nt < 8; nt++) {
                const float b0 = Ks[(nt * 8 + g) * 68 + k0 + t4];
                const float b1 = Ks[(nt * 8 + g) * 68 + k0 + t4 + 4];
                mma8(sacc[nt], qa[kt], b0, b1);
            }
        }
        // online softmax
        float mx0 = -1e30f, mx1 = -1e30f;
        #pragma unroll
        for (int nt = 0; nt < 8; nt++) {
            mx0 = fmaxf(mx0, fmaxf(sacc[nt][0], sacc[nt][1]));
            mx1 = fmaxf(mx1, fmaxf(sacc[nt][2], sacc[nt][3]));
        }
        mx0 = fmaxf(mx0, __shfl_xor_sync(0xffffffffu, mx0, 1));
        mx0 = fmaxf(mx0, __shfl_xor_sync(0xffffffffu, mx0, 2));
        mx1 = fmaxf(mx1, __shfl_xor_sync(0xffffffffu, mx1, 1));
        mx1 = fmaxf(mx1, __shfl_xor_sync(0xffffffffu, mx1, 2));
        const float nm0 = fmaxf(m0, mx0), nm1 = fmaxf(m1, mx1);
        const float c0 = fexp(m0 - nm0), c1 = fexp(m1 - nm1);
        m0 = nm0; m1 = nm1;
        float rs0 = 0.f, rs1 = 0.f;
        #pragma unroll
        for (int nt = 0; nt < 8; nt++) {
            float p0 = fexp(sacc[nt][0] - nm0);
            float p1 = fexp(sacc[nt][1] - nm0);
            float p2 = fexp(sacc[nt][2] - nm1);
            float p3 = fexp(sacc[nt][3] - nm1);
            rs0 += p0 + p1; rs1 += p2 + p3;
            float* pr0 = Ps + (wr0 + g) * 68 + nt * 8 + 2 * t4;
            pr0[0] = tf32r(p0); pr0[1] = tf32r(p1);
            float* pr1 = Ps + (wr0 + g + 8) * 68 + nt * 8 + 2 * t4;
            pr1[0] = tf32r(p2); pr1[1] = tf32r(p3);
            oacc[nt][0] *= c0; oacc[nt][1] *= c0;
            oacc[nt][2] *= c1; oacc[nt][3] *= c1;
        }
        rs0 += __shfl_xor_sync(0xffffffffu, rs0, 1);
        rs0 += __shfl_xor_sync(0xffffffffu, rs0, 2);
        rs1 += __shfl_xor_sync(0xffffffffu, rs1, 1);
        rs1 += __shfl_xor_sync(0xffffffffu, rs1, 2);
        l0 = l0 * c0 + rs0;
        l1 = l1 * c1 + rs1;
        __syncwarp();

        // O += P V
        #pragma unroll
        for (int kt = 0; kt < 8; kt++) {
            const int k0 = kt * 8;
            float pa[4];
            pa[0] = Ps[(wr0 + g) * 68 + k0 + t4];
            pa[1] = Ps[(wr0 + g + 8) * 68 + k0 + t4];
            pa[2] = Ps[(wr0 + g) * 68 + k0 + t4 + 4];
            pa[3] = Ps[(wr0 + g + 8) * 68 + k0 + t4 + 4];
            #pragma unroll
            for (int nt = 0; nt < 8; nt++) {
                const float b0 = Vs[(nt * 8 + g) * 68 + k0 + t4];
                const float b1 = Vs[(nt * 8 + g) * 68 + k0 + t4 + 4];
                mma8(oacc[nt], pa, b0, b1);
            }
        }
        __syncthreads();   // next-buffer stores visible; this buffer free for jt+2
    }

    const float inv0 = __fdividef(1.f, l0), inv1 = __fdividef(1.f, l1);
    #pragma unroll
    for (int nt = 0; nt < 8; nt++) {
        const int col = hh * 64 + nt * 8 + 2 * t4;
        size_t gr0 = ((size_t)(b * Lsz) + i0 + wr0 + g) * 4096 + 3072 + col;
        size_t gr1 = gr0 + (size_t)8 * 4096;
        float2 gv0 = *(const float2*)(qkvg + gr0);
        float2 gv1 = *(const float2*)(qkvg + gr1);
        size_t r0 = ((size_t)(b * Lsz) + i0 + wr0 + g) * Dsz + col;
        size_t r1 = r0 + (size_t)8 * Dsz;
        float2 o0, o1;
        o0.x = tf32r(oacc[nt][0] * inv0 * sigmoidf_(gv0.x));
        o0.y = tf32r(oacc[nt][1] * inv0 * sigmoidf_(gv0.y));
        o1.x = tf32r(oacc[nt][2] * inv1 * sigmoidf_(gv1.x));
        o1.y = tf32r(oacc[nt][3] * inv1 * sigmoidf_(gv1.y));
        *(float2*)(y + r0) = o0;
        *(float2*)(y + r1) = o1;
    }
}

// ----------------------------- launch -----------------------------
static cudaStream_t s_stream2 = nullptr;
static cudaEvent_t  s_evFork = nullptr, s_evJoin = nullptr;

extern "C" void kernel_launch(void* const* d_in, const int* in_sizes, int n_in,
                              void* d_out, int out_size) {
    const float* h     = (const float*)d_in[0];
    const float* p     = (const float*)d_in[1];
    const float* s     = (const float*)d_in[2];
    const float* sln_g = (const float*)d_in[3];
    const float* sln_b = (const float*)d_in[4];
    const float* s1_w  = (const float*)d_in[5];
    const float* s1_b  = (const float*)d_in[6];
    const float* s2_w  = (const float*)d_in[7];
    const float* s2_b  = (const float*)d_in[8];
    const float* q_w   = (const float*)d_in[9];
    const float* q_b   = (const float*)d_in[10];
    const float* k_w   = (const float*)d_in[11];
    const float* k_b   = (const float*)d_in[12];
    const float* v_w   = (const float*)d_in[13];
    const float* v_b   = (const float*)d_in[14];
    const float* eln_g = (const float*)d_in[15];
    const float* eln_b = (const float*)d_in[16];
    const float* e_w   = (const float*)d_in[17];
    const float* gw    = (const float*)d_in[18];
    const float* gb    = (const float*)d_in[19];
    const float* o_w   = (const float*)d_in[20];
    const float* o_b   = (const float*)d_in[21];
    const float* op_w  = (const float*)d_in[22];
    const float* op_b  = (const float*)d_in[23];
    float* out = (float*)d_out;

    float *hn, *sn, *h2, *qkvg, *vtp, *yp, *gatep, *biasp;
    float *wqkvg, *bqkvg, *ws12i, *bs12i, *wo, *wop, *sr;
    cudaGetSymbolAddress((void**)&hn,    g_hn);
    cudaGetSymbolAddress((void**)&sn,    g_sn);
    cudaGetSymbolAddress((void**)&h2,    g_h2);
    cudaGetSymbolAddress((void**)&qkvg,  g_qkvg);
    cudaGetSymbolAddress((void**)&vtp,   g_vt);
    cudaGetSymbolAddress((void**)&yp,    g_yb);
    cudaGetSymbolAddress((void**)&gatep, g_gate);
    cudaGetSymbolAddress((void**)&biasp, g_bias);
    cudaGetSymbolAddress((void**)&wqkvg, g_wqkvg);
    cudaGetSymbolAddress((void**)&bqkvg, g_bqkvg);
    cudaGetSymbolAddress((void**)&ws12i, g_ws12i);
    cudaGetSymbolAddress((void**)&bs12i, g_bs12i);
    cudaGetSymbolAddress((void**)&wo,    g_wo);
    cudaGetSymbolAddress((void**)&wop,   g_wop);
    cudaGetSymbolAddress((void**)&sr,    g_sr);

    if (!s_stream2) {
        cudaStreamCreateWithFlags(&s_stream2, cudaStreamNonBlocking);
        cudaEventCreateWithFlags(&s_evFork, cudaEventDisableTiming);
        cudaEventCreateWithFlags(&s_evJoin, cudaEventDisableTiming);
        cudaFuncSetAttribute(attn_mma, cudaFuncAttributeMaxDynamicSharedMemorySize, ATTN_SMEM);
    }

    const int M = Bsz * Lsz;           // 2048

    // ---- fork: stream B runs pairbias (tensor-core version) alone ----
    cudaEventRecord(s_evFork, 0);
    cudaStreamWaitEvent(s_stream2, s_evFork, 0);
    pairbias_mma<<<dim3(Lsz / 128, Lsz, Bsz), 128, 0, s_stream2>>>(p, eln_g, eln_b, e_w, biasp);
    cudaEventRecord(s_evJoin, s_stream2);

    // ---- stream A (default): everything else ----
    pack_s12<<<(NDsz * Dsz + 255) / 256, 256>>>(s1_w, s2_w, s1_b, s2_b, ws12i, bs12i);
    pack_qkvg<<<(Dsz * Dsz + 255) / 256, 256>>>(q_w, k_w, v_w, gw, wqkvg);
    cvt_all<<<(Dsz * Dsz + 255) / 256, 256>>>(o_w, wo, op_w, wop, s, sr);
    const float* bsrc[4] = {q_b, k_b, v_b, gb};
    for (int j = 0; j < 4; j++)
        cudaMemcpyAsync(bqkvg + j * 1024, bsrc[j], 1024 * 4, cudaMemcpyDeviceToDevice, 0);

    ln_kernel<<<M, 256>>>(h, nullptr, nullptr, hn, Dsz, 0);
    ln_kernel<<<M, 256>>>(s, sln_g, sln_b, sn, NDsz, 1);

    gemm_tf32<3><<<dim3(2048 / 128, M / 64), 128>>>(sn, ws12i, bs12i, h2, hn, M, 2048, NDsz);
    gemm_tf32<4><<<dim3(4096 / 128, M / 64), 128>>>(h2, wqkvg, bqkvg, qkvg, nullptr, M, 4096, Dsz);
    transpose_kernel<<<dim3(32, 32, Bsz), dim3(32, 8)>>>(qkvg + 2048, vtp);
    gemm_tf32<1><<<dim3(Dsz / 128, M / 64), 128>>>(sr, wop, op_b, gatep, nullptr, M, Dsz, NDsz);

    // ---- join: attention needs pairbias ----
    cudaStreamWaitEvent(0, s_evJoin, 0);

    attn_mma<<<dim3(Lsz / 128, Hsz, Bsz), 256, ATTN_SMEM>>>(qkvg, vtp, biasp, yp);

    // o-projection with fused final gate multiply -> out
    gemm_tf32<5><<<dim3(Dsz / 128, M / 64), 128>>>(yp, wo, o_b, out, gatep, M, Dsz, Dsz);
}

// round 15
// speedup vs baseline: 1.1412x; 1.0134x over previous
#include <cuda_runtime.h>
#include <math.h>
#include <stdint.h>

#define Bsz 2
#define Lsz 1024
#define Dsz 1024
#define Hsz 16
#define Esz 64
#define NDsz 512
#define HDsz 64
#define QSCALE 0.125f   // 1/sqrt(64), exact power of two

// ----------------------------- scratch (device globals, no allocs) -----------------------------
__device__ float g_hn   [Bsz*Lsz*Dsz];
__device__ float g_sn   [Bsz*Lsz*NDsz];
__device__ float g_h2   [Bsz*Lsz*Dsz];
__device__ float g_qkvg [(size_t)Bsz*Lsz*4*Dsz];   // [2048][4096]: q|k|v|graw
__device__ float g_vt   [Bsz*Lsz*Dsz];             // V^T [B][D][L]
__device__ float g_yb   [Bsz*Lsz*Dsz];
__device__ float g_gate [Bsz*Lsz*Dsz];             // sigmoid(s@op_w+op_b)
__device__ float g_bias [(size_t)Bsz*Hsz*Lsz*Lsz]; // 128 MB, [b][h][i][j]
__device__ float g_wqkvg[Dsz*4*Dsz];               // [1024][4096] tf32-rounded
__device__ float g_bqkvg[4*Dsz];
__device__ float g_ws12i[NDsz*2*Dsz];              // [512][2048] interleaved, rounded
__device__ float g_bs12i[2*Dsz];
__device__ float g_wo   [Dsz*Dsz];                 // o_w rounded
__device__ float g_wop  [NDsz*Dsz];                // op_w rounded
__device__ float g_sr   [Bsz*Lsz*NDsz];            // s rounded

// ----------------------------- fast math -----------------------------
__device__ __forceinline__ float fexp(float x) {
    x = fminf(fmaxf(x, -80.f), 80.f);
    float t  = x * 1.44269504f;
    float fj = t + 12582912.f;
    int   i  = __float_as_int(fj) - 0x4B400000;
    float j  = fj - 12582912.f;
    float f  = t - j;
    float u  = f * 0.69314718f;
    float p  = 1.f + u * (1.f + u * (0.5f + u * (0.166666667f +
               u * (0.0416666667f + u * 0.00833333333f))));
    return p * __int_as_float((i + 127) << 23);
}
__device__ __forceinline__ float sigmoidf_(float x) {
    return __fdividef(1.0f, 1.0f + fexp(-x));
}
__device__ __forceinline__ float tf32r(float x) {
    uint32_t u;
    asm("cvt.rna.tf32.f32 %0, %1;" : "=r"(u) : "f"(x));
    return __uint_as_float(u);
}
__device__ __forceinline__ void mma8(float* d, const float* a, float b0f, float b1f) {
    const uint32_t* A = (const uint32_t*)a;
    uint32_t B0 = __float_as_uint(b0f), B1 = __float_as_uint(b1f);
    asm volatile(
        "mma.sync.aligned.m16n8k8.row.col.f32.tf32.tf32.f32 "
        "{%0,%1,%2,%3}, {%4,%5,%6,%7}, {%8,%9}, {%0,%1,%2,%3};\n"
        : "+f"(d[0]), "+f"(d[1]), "+f"(d[2]), "+f"(d[3])
        : "r"(A[0]), "r"(A[1]), "r"(A[2]), "r"(A[3]), "r"(B0), "r"(B1));
}

// ----------------------------- pack / convert kernels -----------------------------
__global__ void pack_s12(const float* __restrict__ s1w, const float* __restrict__ s2w,
                         const float* __restrict__ s1b, const float* __restrict__ s2b,
                         float* __restrict__ wi, float* __restrict__ bi) {
    int i = blockIdx.x * 256 + threadIdx.x;
    if (i < NDsz * Dsz) {
        int k = i >> 10, f = i & 1023;
        float2 v; v.x = tf32r(s1w[i]); v.y = tf32r(s2w[i]);
        *(float2*)(wi + (size_t)k * 2048 + 2 * f) = v;
    }
    if (i < Dsz) { bi[2 * i] = s1b[i]; bi[2 * i + 1] = s2b[i]; }
}
__global__ void pack_qkvg(const float* __restrict__ qw, const float* __restrict__ kw,
                          const float* __restrict__ vw, const float* __restrict__ gw,
                          float* __restrict__ w) {
    int i = blockIdx.x * 256 + threadIdx.x;
    if (i < Dsz * Dsz) {
        int r = i >> 10, c = i & 1023;
        float* o = w + (size_t)r * 4096;
        o[c]        = tf32r(qw[i]);
        o[1024 + c] = tf32r(kw[i]);
        o[2048 + c] = tf32r(vw[i]);
        o[3072 + c] = tf32r(gw[i]);
    }
}
__global__ void cvt_all(const float* __restrict__ ow, float* __restrict__ dow,
                        const float* __restrict__ opw, float* __restrict__ dopw,
                        const float* __restrict__ s, float* __restrict__ dsr) {
    int i = blockIdx.x * 256 + threadIdx.x;
    if (i < Dsz * Dsz)   dow[i]  = tf32r(ow[i]);
    if (i < NDsz * Dsz)  dopw[i] = tf32r(opw[i]);
    if (i < Bsz * Lsz * NDsz) dsr[i] = tf32r(s[i]);
}

// ----------------------------- LayerNorm -----------------------------
__global__ void ln_kernel(const float* __restrict__ x, const float* __restrict__ g,
                          const float* __restrict__ b, float* __restrict__ y, int C, int rnd) {
    __shared__ float red[64];
    const int row = blockIdx.x;
    const float* xr = x + (size_t)row * C;
    float sum = 0.f, sq = 0.f;
    for (int i = threadIdx.x; i < C; i += 256) {
        float v = xr[i];
        sum += v; sq += v * v;
    }
    #pragma unroll
    for (int off = 16; off; off >>= 1) {
        sum += __shfl_xor_sync(0xffffffffu, sum, off);
        sq  += __shfl_xor_sync(0xffffffffu, sq,  off);
    }
    int w = threadIdx.x >> 5, lane = threadIdx.x & 31;
    if (lane == 0) { red[w] = sum; red[w + 32] = sq; }
    __syncthreads();
    if (w == 0) {
        float s1 = (lane < 8) ? red[lane] : 0.f;
        float s2 = (lane < 8) ? red[lane + 32] : 0.f;
        #pragma unroll
        for (int off = 4; off; off >>= 1) {
            s1 += __shfl_xor_sync(0xffffffffu, s1, off);
            s2 += __shfl_xor_sync(0xffffffffu, s2, off);
        }
        if (lane == 0) { red[0] = s1; red[1] = s2; }
    }
    __syncthreads();
    float mean = red[0] / (float)C;
    float var  = red[1] / (float)C - mean * mean;
    float inv  = rsqrtf(var + 1e-5f);
    float* yr = y + (size_t)row * C;
    for (int i = threadIdx.x; i < C; i += 256) {
        float v = (xr[i] - mean) * inv;
        if (g) v = v * g[i] + b[i];
        yr[i] = rnd ? tf32r(v) : v;
    }
}

// ----------------------------- tf32 GEMM 64x128x16, 128 threads, 4 blocks/SM -----------------
// EPI 0: C = A@B + bias
// EPI 1: C = sigmoid(A@B + bias)
// EPI 3: h2 = tf32r(sigmoid(even+bE)*aux + (odd+bO))     (interleaved; C,aux stride N/2)
// EPI 4: like 0 but rounds output for cols < 3*N/4 (q,k,v rounded; gate raw)
// EPI 5: C = (A@B + bias) * aux                          (final output gate multiply)
template<int EPI>
__global__ void __launch_bounds__(128, 4)
gemm_tf32(const float* __restrict__ A, const float* __restrict__ B,
          const float* __restrict__ bias, float* __restrict__ C,
          const float* __restrict__ aux, int M, int N, int K) {
    __shared__ __align__(16) float As[2][64][20];
    __shared__ __align__(16) float Bs[2][16][136];
    const int tid  = threadIdx.x;
    const int wid  = tid >> 5, lane = tid & 31;
    const int g    = lane >> 2, t4 = lane & 3;
    const int wm   = (wid & 1) * 32;
    const int wn   = (wid >> 1) * 64;
    const int bx   = blockIdx.x, by = blockIdx.y;

    const int ar = tid >> 2, ac = (tid & 3) * 4;
    const int br = tid >> 5, bc = (tid & 31) * 4;
    const float* Ag = A + ((size_t)(by * 64 + ar)) * K + ac;
    const float* Bg = B + (size_t)br * N + bx * 128 + bc;

    float acc[2][8][4];
    #pragma unroll
    for (int mt = 0; mt < 2; mt++)
        #pragma unroll
        for (int nt = 0; nt < 8; nt++)
            #pragma unroll
            for (int c = 0; c < 4; c++) acc[mt][nt][c] = 0.f;

    float4 ra0, ra1, rb[4];
    ra0 = *(const float4*)(Ag);
    ra1 = *(const float4*)(Ag + (size_t)32 * K);
    #pragma unroll
    for (int i = 0; i < 4; i++)
        rb[i] = *(const float4*)(Bg + (size_t)(4 * i) * N);

    *(float4*)&As[0][ar][ac]      = ra0;
    *(float4*)&As[0][ar + 32][ac] = ra1;
    #pragma unroll
    for (int i = 0; i < 4; i++)
        *(float4*)&Bs[0][br + 4 * i][bc] = rb[i];
    __syncthreads();

    const int nk = K >> 4;
    for (int it = 0; it < nk; it++) {
        const int buf = it & 1;
        if (it + 1 < nk) {
            const float* Ag2 = Ag + (it + 1) * 16;
            ra0 = *(const float4*)(Ag2);
            ra1 = *(const float4*)(Ag2 + (size_t)32 * K);
            const float* Bg2 = Bg + (size_t)(it + 1) * 16 * N;
            #pragma unroll
            for (int i = 0; i < 4; i++)
                rb[i] = *(const float4*)(Bg2 + (size_t)(4 * i) * N);
        }
        #pragma unroll
        for (int ks = 0; ks < 2; ks++) {
            const int k0 = ks * 8;
            float a[2][4];
            #pragma unroll
            for (int mt = 0; mt < 2; mt++) {
                const int m0 = wm + mt * 16;
                a[mt][0] = As[buf][m0 + g][k0 + t4];
                a[mt][1] = As[buf][m0 + g + 8][k0 + t4];
                a[mt][2] = As[buf][m0 + g][k0 + t4 + 4];
                a[mt][3] = As[buf][m0 + g + 8][k0 + t4 + 4];
            }
            #pragma unroll
            for (int nt = 0; nt < 8; nt++) {
                const float b0 = Bs[buf][k0 + t4][wn + nt * 8 + g];
                const float b1 = Bs[buf][k0 + t4 + 4][wn + nt * 8 + g];
                mma8(acc[0][nt], a[0], b0, b1);
                mma8(acc[1][nt], a[1], b0, b1);
            }
        }
        if (it + 1 < nk) {
            const int nb = buf ^ 1;
            *(float4*)&As[nb][ar][ac]      = ra0;
            *(float4*)&As[nb][ar + 32][ac] = ra1;
            #pragma unroll
            for (int i = 0; i < 4; i++)
                *(float4*)&Bs[nb][br + 4 * i][bc] = rb[i];
        }
        __syncthreads();
    }

    #pragma unroll
    for (int mt = 0; mt < 2; mt++) {
        #pragma unroll
        for (int nt = 0; nt < 8; nt++) {
            const int row0 = by * 64 + wm + mt * 16 + g;
            const int col  = bx * 128 + wn + nt * 8 + 2 * t4;
            const float b0 = bias[col], b1 = bias[col + 1];
            if (EPI == 3) {
                const int f = col >> 1;
                const int ldc = N >> 1;
                float e0 = acc[mt][nt][0] + b0, o0 = acc[mt][nt][1] + b1;
                float e1 = acc[mt][nt][2] + b0, o1 = acc[mt][nt][3] + b1;
                C[(size_t)row0 * ldc + f]       = tf32r(sigmoidf_(e0) * aux[(size_t)row0 * ldc + f] + o0);
                C[(size_t)(row0 + 8) * ldc + f] = tf32r(sigmoidf_(e1) * aux[(size_t)(row0 + 8) * ldc + f] + o1);
            } else {
                float2 o0, o1;
                o0.x = acc[mt][nt][0] + b0; o0.y = acc[mt][nt][1] + b1;
                o1.x = acc[mt][nt][2] + b0; o1.y = acc[mt][nt][3] + b1;
                if (EPI == 1) {
                    o0.x = sigmoidf_(o0.x); o0.y = sigmoidf_(o0.y);
                    o1.x = sigmoidf_(o1.x); o1.y = sigmoidf_(o1.y);
                } else if (EPI == 5) {
                    float2 x0 = *(const float2*)(aux + (size_t)row0 * N + col);
                    float2 x1 = *(const float2*)(aux + (size_t)(row0 + 8) * N + col);
                    o0.x *= x0.x; o0.y *= x0.y;
                    o1.x *= x1.x; o1.y *= x1.y;
                } else if (EPI == 4) {
                    if (col < (3 * N) / 4) {
                        o0.x = tf32r(o0.x); o0.y = tf32r(o0.y);
                        o1.x = tf32r(o1.x); o1.y = tf32r(o1.y);
                    }
                }
                *(float2*)(C + (size_t)row0 * N + col)       = o0;
                *(float2*)(C + (size_t)(row0 + 8) * N + col) = o1;
            }
        }
    }
}

// ----------------------------- V transpose: packed qkvg v-slice -> [B][D][L] ---------------------
__global__ void transpose_kernel(const float* __restrict__ src, float* __restrict__ dst) {
    __shared__ float tile[32][33];
    const int b = blockIdx.z;
    const int x0 = blockIdx.x * 32;
    const int y0 = blockIdx.y * 32;
    const int tx = threadIdx.x, ty = threadIdx.y;
    #pragma unroll
    for (int i = 0; i < 32; i += 8)
        tile[ty + i][tx] = src[((size_t)b * Lsz + y0 + ty + i) * 4096 + x0 + tx];
    __syncthreads();
    #pragma unroll
    for (int i = 0; i < 32; i += 8)
        dst[((size_t)b * Dsz + x0 + ty + i) * Lsz + y0 + tx] = tile[tx][ty + i];
}

// ----------------------------- pair bias via tensor cores -----------------------------
__global__ void __launch_bounds__(128)
pairbias_mma(const float* __restrict__ p, const float* __restrict__ eg,
             const float* __restrict__ eb, const float* __restrict__ ew,
             float* __restrict__ bias) {
    __shared__ __align__(16) float xs[128 * 68];
    __shared__ float sew[Esz * Hsz];
    __shared__ float seg[Esz], seb[Esz];
    const int tid = threadIdx.x, wid = tid >> 5, lane = tid & 31;
    const int g = lane >> 2, t4 = lane & 3;
    const int b = blockIdx.z, i = blockIdx.y, j0 = blockIdx.x * 128;

    float4 pr[16];
    const float4* prow = (const float4*)(p + (((size_t)b * Lsz + i) * Lsz + j0 + tid) * Esz);
    #pragma unroll
    for (int c = 0; c < 16; c++) pr[c] = prow[c];

    for (int t = tid; t < Esz * Hsz; t += 128) sew[t] = tf32r(ew[t]);
    if (tid < Esz) { seg[tid] = eg[tid]; seb[tid] = eb[tid]; }
    __syncthreads();

    float sum = 0.f, sq = 0.f;
    #pragma unroll
    for (int c = 0; c < 16; c++) {
        sum += pr[c].x + pr[c].y + pr[c].z + pr[c].w;
        sq  += pr[c].x * pr[c].x + pr[c].y * pr[c].y + pr[c].z * pr[c].z + pr[c].w * pr[c].w;
    }
    float mean = sum * (1.f / 64.f);
    float var  = sq * (1.f / 64.f) - mean * mean;
    float inv  = rsqrtf(var + 1e-5f);

    float* xrow = xs + tid * 68;
    #pragma unroll
    for (int c = 0; c < 16; c++) {
        float4 o;
        int e = c * 4;
        o.x = tf32r((pr[c].x - mean) * inv * seg[e + 0] + seb[e + 0]);
        o.y = tf32r((pr[c].y - mean) * inv * seg[e + 1] + seb[e + 1]);
        o.z = tf32r((pr[c].z - mean) * inv * seg[e + 2] + seb[e + 2]);
        o.w = tf32r((pr[c].w - mean) * inv * seg[e + 3] + seb[e + 3]);
        *(float4*)(xrow + e) = o;
    }
    __syncthreads();

    float acc[2][2][4];
    #pragma unroll
    for (int m = 0; m < 2; m++)
        #pragma unroll
        for (int n = 0; n < 2; n++)
            #pragma unroll
            for (int c = 0; c < 4; c++) acc[m][n][c] = 0.f;

    #pragma unroll
    for (int k = 0; k < 8; k++) {
        const int k0 = k * 8;
        float a[2][4];
        #pragma unroll
        for (int m = 0; m < 2; m++) {
            const int m0 = wid * 32 + m * 16;
            a[m][0] = xs[(m0 + g) * 68 + k0 + t4];
            a[m][1] = xs[(m0 + g + 8) * 68 + k0 + t4];
            a[m][2] = xs[(m0 + g) * 68 + k0 + t4 + 4];
            a[m][3] = xs[(m0 + g + 8) * 68 + k0 + t4 + 4];
        }
        #pragma unroll
        for (int n = 0; n < 2; n++) {
            const float b0 = sew[(k0 + t4) * 16 + n * 8 + g];
            const float b1 = sew[(k0 + t4 + 4) * 16 + n * 8 + g];
            mma8(acc[0][n], a[0], b0, b1);
            mma8(acc[1][n], a[1], b0, b1);
        }
    }

    const size_t LL = (size_t)Lsz * Lsz;
    #pragma unroll
    for (int m = 0; m < 2; m++) {
        const int jg = j0 + wid * 32 + m * 16 + g;
        #pragma unroll
        for (int n = 0; n < 2; n++) {
            const int h0 = n * 8 + 2 * t4;
            size_t base = ((size_t)(b * Hsz + h0) * Lsz + i) * Lsz;
            bias[base + jg]          = acc[m][n][0];
            bias[base + LL + jg]     = acc[m][n][1];
            bias[base + jg + 8]      = acc[m][n][2];
            bias[base + LL + jg + 8] = acc[m][n][3];
        }
    }
}

// ----------------------------- flash attention (double-buffered K/V, Q direct) ---------------
#define ATTN_SMEM ((4 * 4352 + 128 * 68) * 4)   // K[2]+V[2] + Ps(P only) = 104448 B
__global__ void __launch_bounds__(256)
attn_mma(const float* __restrict__ qkvg, const float* __restrict__ vt,
         const float* __restrict__ bias, float* __restrict__ y) {
    extern __shared__ __align__(16) float smx[];
    float* Ps = smx + 17408;   // [128][68] P staging

    const int b = blockIdx.z, hh = blockIdx.y, i0 = blockIdx.x * 128;
    const int tid = threadIdx.x, wid = tid >> 5, lane = tid & 31;
    const int g = lane >> 2, t4 = lane & 3;
    const int wr0 = wid * 16;
    const int sr = tid >> 4, sc = (tid & 15) * 4;

    // Q fragments directly from gmem (q pre-rounded tf32; *2^-3 exact)
    float qa[8][4];
    {
        const float* qrow0 = qkvg + ((size_t)(b * Lsz) + i0 + wr0 + g) * 4096 + hh * 64;
        const float* qrow1 = qrow0 + (size_t)8 * 4096;
        #pragma unroll
        for (int kt = 0; kt < 8; kt++) {
            qa[kt][0] = qrow0[kt * 8 + t4] * QSCALE;
            qa[kt][1] = qrow1[kt * 8 + t4] * QSCALE;
            qa[kt][2] = qrow0[kt * 8 + t4 + 4] * QSCALE;
            qa[kt][3] = qrow1[kt * 8 + t4 + 4] * QSCALE;
        }
    }
    float oacc[8][4];
    #pragma unroll
    for (int nt = 0; nt < 8; nt++)
        #pragma unroll
        for (int c = 0; c < 4; c++) oacc[nt][c] = 0.f;
    float m0 = -1e30f, m1 = -1e30f, l0 = 0.f, l1 = 0.f;

    const float* brow0 = bias + (((size_t)(b * Hsz + hh)) * Lsz + i0 + wr0 + g) * Lsz;
    const float* brow1 = brow0 + (size_t)8 * Lsz;
    const float* kbase = qkvg + (size_t)(b * Lsz) * 4096 + 1024 + hh * 64;
    const float* vbase = vt + ((size_t)(b * Dsz) + hh * 64) * Lsz;

    // stage tile 0 into buffer 0
    for (int rr = sr; rr < 64; rr += 16) {
        float4 kv = *(const float4*)(kbase + (size_t)rr * 4096 + sc);
        *(float4*)(smx + rr * 68 + sc) = kv;
        float4 vv = *(const float4*)(vbase + (size_t)rr * Lsz + sc);
        *(float4*)(smx + 8704 + rr * 68 + sc) = vv;
    }
    __syncthreads();

    for (int jt = 0; jt < 16; jt++) {
        const int jb = jt * 64;
        const int buf = jt & 1;
        float* Ks = smx + buf * 4352;
        float* Vs = smx + 8704 + buf * 4352;

        // issue next tile's copy into the free buffer (drains under compute)
        if (jt + 1 < 16) {
            float* Kn = smx + (buf ^ 1) * 4352;
            float* Vn = smx + 8704 + (buf ^ 1) * 4352;
            const int jn = jb + 64;
            for (int rr = sr; rr < 64; rr += 16) {
                float4 kv = *(const float4*)(kbase + (size_t)(jn + rr) * 4096 + sc);
                *(float4*)(Kn + rr * 68 + sc) = kv;
                float4 vv = *(const float4*)(vbase + (size_t)rr * Lsz + jn + sc);
                *(float4*)(Vn + rr * 68 + sc) = vv;
            }
        }

        // S = Q K^T + bias
        float sacc[8][4];
        #pragma unroll
        for (int nt = 0; nt < 8; nt++) {
            float2 bb0 = *(const float2*)(brow0 + jb + nt * 8 + 2 * t4);
            float2 bb1 = *(const float2*)(brow1 + jb + nt * 8 + 2 * t4);
            sacc[nt][0] = bb0.x; sacc[nt][1] = bb0.y;
            sacc[nt][2] = bb1.x; sacc[nt][3] = bb1.y;
        }
        #pragma unroll
        for (int kt = 0; kt < 8; kt++) {
            const int k0 = kt * 8;
            #pragma unroll
            for (int nt = 0; nt < 8; nt++) {
                const float b0 = Ks[(nt * 8 + g) * 68 + k0 + t4];
                const float b1 = Ks[(nt * 8 + g) * 68 + k0 + t4 + 4];
                mma8(sacc[nt], qa[kt], b0, b1);
            }
        }
        // online softmax
        float mx0 = -1e30f, mx1 = -1e30f;
        #pragma unroll
        for (int nt = 0; nt < 8; nt++) {
            mx0 = fmaxf(mx0, fmaxf(sacc[nt][0], sacc[nt][1]));
            mx1 = fmaxf(mx1, fmaxf(sacc[nt][2], sacc[nt][3]));
        }
        mx0 = fmaxf(mx0, __shfl_xor_sync(0xffffffffu, mx0, 1));
        mx0 = fmaxf(mx0, __shfl_xor_sync(0xffffffffu, mx0, 2));
        mx1 = fmaxf(mx1, __shfl_xor_sync(0xffffffffu, mx1, 1));
        mx1 = fmaxf(mx1, __shfl_xor_sync(0xffffffffu, mx1, 2));
        const float nm0 = fmaxf(m0, mx0), nm1 = fmaxf(m1, mx1);
        const float c0 = fexp(m0 - nm0), c1 = fexp(m1 - nm1);
        m0 = nm0; m1 = nm1;
        float rs0 = 0.f, rs1 = 0.f;
        #pragma unroll
        for (int nt = 0; nt < 8; nt++) {
            float p0 = fexp(sacc[nt][0] - nm0);
            float p1 = fexp(sacc[nt][1] - nm0);
            float p2 = fexp(sacc[nt][2] - nm1);
            float p3 = fexp(sacc[nt][3] - nm1);
            rs0 += p0 + p1; rs1 += p2 + p3;
            float* pr0 = Ps + (wr0 + g) * 68 + nt * 8 + 2 * t4;
            pr0[0] = tf32r(p0); pr0[1] = tf32r(p1);
            float* pr1 = Ps + (wr0 + g + 8) * 68 + nt * 8 + 2 * t4;
            pr1[0] = tf32r(p2); pr1[1] = tf32r(p3);
            oacc[nt][0] *= c0; oacc[nt][1] *= c0;
            oacc[nt][2] *= c1; oacc[nt][3] *= c1;
        }
        rs0 += __shfl_xor_sync(0xffffffffu, rs0, 1);
        rs0 += __shfl_xor_sync(0xffffffffu, rs0, 2);
        rs1 += __shfl_xor_sync(0xffffffffu, rs1, 1);
        rs1 += __shfl_xor_sync(0xffffffffu, rs1, 2);
        l0 = l0 * c0 + rs0;
        l1 = l1 * c1 + rs1;
        __syncwarp();

        // O += P V
        #pragma unroll
        for (int kt = 0; kt < 8; kt++) {
            const int k0 = kt * 8;
            float pa[4];
            pa[0] = Ps[(wr0 + g) * 68 + k0 + t4];
            pa[1] = Ps[(wr0 + g + 8) * 68 + k0 + t4];
            pa[2] = Ps[(wr0 + g) * 68 + k0 + t4 + 4];
            pa[3] = Ps[(wr0 + g + 8) * 68 + k0 + t4 + 4];
            #pragma unroll
            for (int nt = 0; nt < 8; nt++) {
                const float b0 = Vs[(nt * 8 + g) * 68 + k0 + t4];
                const float b1 = Vs[(nt * 8 + g) * 68 + k0 + t4 + 4];
                mma8(oacc[nt], pa, b0, b1);
            }
        }
        __syncthreads();   // next-buffer stores visible; this buffer free for jt+2
    }

    const float inv0 = __fdividef(1.f, l0), inv1 = __fdividef(1.f, l1);
    #pragma unroll
    for (int nt = 0; nt < 8; nt++) {
        const int col = hh * 64 + nt * 8 + 2 * t4;
        size_t gr0 = ((size_t)(b * Lsz) + i0 + wr0 + g) * 4096 + 3072 + col;
        size_t gr1 = gr0 + (size_t)8 * 4096;
        float2 gv0 = *(const float2*)(qkvg + gr0);
        float2 gv1 = *(const float2*)(qkvg + gr1);
        size_t r0 = ((size_t)(b * Lsz) + i0 + wr0 + g) * Dsz + col;
        size_t r1 = r0 + (size_t)8 * Dsz;
        float2 o0, o1;
        o0.x = tf32r(oacc[nt][0] * inv0 * sigmoidf_(gv0.x));
        o0.y = tf32r(oacc[nt][1] * inv0 * sigmoidf_(gv0.y));
        o1.x = tf32r(oacc[nt][2] * inv1 * sigmoidf_(gv1.x));
        o1.y = tf32r(oacc[nt][3] * inv1 * sigmoidf_(gv1.y));
        *(float2*)(y + r0) = o0;
        *(float2*)(y + r1) = o1;
    }
}

// ----------------------------- launch -----------------------------
static cudaStream_t s_stream2 = nullptr;
static cudaEvent_t  s_evFork = nullptr, s_evJoin = nullptr;

extern "C" void kernel_launch(void* const* d_in, const int* in_sizes, int n_in,
                              void* d_out, int out_size) {
    const float* h     = (const float*)d_in[0];
    const float* p     = (const float*)d_in[1];
    const float* s     = (const float*)d_in[2];
    const float* sln_g = (const float*)d_in[3];
    const float* sln_b = (const float*)d_in[4];
    const float* s1_w  = (const float*)d_in[5];
    const float* s1_b  = (const float*)d_in[6];
    const float* s2_w  = (const float*)d_in[7];
    const float* s2_b  = (const float*)d_in[8];
    const float* q_w   = (const float*)d_in[9];
    const float* q_b   = (const float*)d_in[10];
    const float* k_w   = (const float*)d_in[11];
    const float* k_b   = (const float*)d_in[12];
    const float* v_w   = (const float*)d_in[13];
    const float* v_b   = (const float*)d_in[14];
    const float* eln_g = (const float*)d_in[15];
    const float* eln_b = (const float*)d_in[16];
    const float* e_w   = (const float*)d_in[17];
    const float* gw    = (const float*)d_in[18];
    const float* gb    = (const float*)d_in[19];
    const float* o_w   = (const float*)d_in[20];
    const float* o_b   = (const float*)d_in[21];
    const float* op_w  = (const float*)d_in[22];
    const float* op_b  = (const float*)d_in[23];
    float* out = (float*)d_out;

    float *hn, *sn, *h2, *qkvg, *vtp, *yp, *gatep, *biasp;
    float *wqkvg, *bqkvg, *ws12i, *bs12i, *wo, *wop, *sr;
    cudaGetSymbolAddress((void**)&hn,    g_hn);
    cudaGetSymbolAddress((void**)&sn,    g_sn);
    cudaGetSymbolAddress((void**)&h2,    g_h2);
    cudaGetSymbolAddress((void**)&qkvg,  g_qkvg);
    cudaGetSymbolAddress((void**)&vtp,   g_vt);
    cudaGetSymbolAddress((void**)&yp,    g_yb);
    cudaGetSymbolAddress((void**)&gatep, g_gate);
    cudaGetSymbolAddress((void**)&biasp, g_bias);
    cudaGetSymbolAddress((void**)&wqkvg, g_wqkvg);
    cudaGetSymbolAddress((void**)&bqkvg, g_bqkvg);
    cudaGetSymbolAddress((void**)&ws12i, g_ws12i);
    cudaGetSymbolAddress((void**)&bs12i, g_bs12i);
    cudaGetSymbolAddress((void**)&wo,    g_wo);
    cudaGetSymbolAddress((void**)&wop,   g_wop);
    cudaGetSymbolAddress((void**)&sr,    g_sr);

    if (!s_stream2) {
        cudaStreamCreateWithFlags(&s_stream2, cudaStreamNonBlocking);
        cudaEventCreateWithFlags(&s_evFork, cudaEventDisableTiming);
        cudaEventCreateWithFlags(&s_evJoin, cudaEventDisableTiming);
        cudaFuncSetAttribute(attn_mma, cudaFuncAttributeMaxDynamicSharedMemorySize, ATTN_SMEM);
    }

    const int M = Bsz * Lsz;           // 2048

    // ---- fork: stream B runs pairbias (tensor-core version) alone ----
    cudaEventRecord(s_evFork, 0);
    cudaStreamWaitEvent(s_stream2, s_evFork, 0);
    pairbias_mma<<<dim3(Lsz / 128, Lsz, Bsz), 128, 0, s_stream2>>>(p, eln_g, eln_b, e_w, biasp);
    cudaEventRecord(s_evJoin, s_stream2);

    // ---- stream A (default): everything else ----
    pack_s12<<<(NDsz * Dsz + 255) / 256, 256>>>(s1_w, s2_w, s1_b, s2_b, ws12i, bs12i);
    pack_qkvg<<<(Dsz * Dsz + 255) / 256, 256>>>(q_w, k_w, v_w, gw, wqkvg);
    cvt_all<<<(Dsz * Dsz + 255) / 256, 256>>>(o_w, wo, op_w, wop, s, sr);
    const float* bsrc[4] = {q_b, k_b, v_b, gb};
    for (int j = 0; j < 4; j++)
        cudaMemcpyAsync(bqkvg + j * 1024, bsrc[j], 1024 * 4, cudaMemcpyDeviceToDevice, 0);

    ln_kernel<<<M, 256>>>(h, nullptr, nullptr, hn, Dsz, 0);
    ln_kernel<<<M, 256>>>(s, sln_g, sln_b, sn, NDsz, 1);

    gemm_tf32<3><<<dim3(2048 / 128, M / 64), 128>>>(sn, ws12i, bs12i, h2, hn, M, 2048, NDsz);
    gemm_tf32<4><<<dim3(4096 / 128, M / 64), 128>>>(h2, wqkvg, bqkvg, qkvg, nullptr, M, 4096, Dsz);
    transpose_kernel<<<dim3(32, 32, Bsz), dim3(32, 8)>>>(qkvg + 2048, vtp);
    gemm_tf32<1><<<dim3(Dsz / 128, M / 64), 128>>>(sr, wop, op_b, gatep, nullptr, M, Dsz, NDsz);

    // ---- join: attention needs pairbias ----
    cudaStreamWaitEvent(0, s_evJoin, 0);

    attn_mma<<<dim3(Lsz / 128, Hsz, Bsz), 256, ATTN_SMEM>>>(qkvg, vtp, biasp, yp);

    // o-projection with fused final gate multiply -> out
    gemm_tf32<5><<<dim3(Dsz / 128, M / 64), 128>>>(yp, wo, o_b, out, gatep, M, Dsz, Dsz);
}

// round 16
// speedup vs baseline: 1.1518x; 1.0093x over previous
#include <cuda_runtime.h>
#include <math.h>
#include <stdint.h>

#define Bsz 2
#define Lsz 1024
#define Dsz 1024
#define Hsz 16
#define Esz 64
#define NDsz 512
#define HDsz 64
#define QSCALE 0.125f   // 1/sqrt(64), exact power of two

// ----------------------------- scratch (device globals, no allocs) -----------------------------
__device__ float g_hn   [Bsz*Lsz*Dsz];
__device__ float g_sn   [Bsz*Lsz*NDsz];
__device__ float g_h2   [Bsz*Lsz*Dsz];
__device__ float g_qkvg [(size_t)Bsz*Lsz*4*Dsz];   // [2048][4096]: q|k|v|graw
__device__ float g_vt   [Bsz*Lsz*Dsz];             // V^T [B][D][L]
__device__ float g_yb   [Bsz*Lsz*Dsz];
__device__ float g_gate [Bsz*Lsz*Dsz];             // sigmoid(s@op_w+op_b)
__device__ float g_bias [(size_t)Bsz*Hsz*Lsz*Lsz]; // 128 MB, [b][h][i][j]
__device__ float g_wqkvg[Dsz*4*Dsz];               // [1024][4096] tf32-rounded
__device__ float g_bqkvg[4*Dsz];
__device__ float g_ws12i[NDsz*2*Dsz];              // [512][2048] interleaved, rounded
__device__ float g_bs12i[2*Dsz];
__device__ float g_wo   [Dsz*Dsz];                 // o_w rounded
__device__ float g_wop  [NDsz*Dsz];                // op_w rounded
__device__ float g_sr   [Bsz*Lsz*NDsz];            // s rounded

// ----------------------------- fast math -----------------------------
__device__ __forceinline__ float fexp(float x) {
    x = fminf(fmaxf(x, -80.f), 80.f);
    float t  = x * 1.44269504f;
    float fj = t + 12582912.f;
    int   i  = __float_as_int(fj) - 0x4B400000;
    float j  = fj - 12582912.f;
    float f  = t - j;
    float u  = f * 0.69314718f;
    float p  = 1.f + u * (1.f + u * (0.5f + u * (0.166666667f +
               u * (0.0416666667f + u * 0.00833333333f))));
    return p * __int_as_float((i + 127) << 23);
}
__device__ __forceinline__ float sigmoidf_(float x) {
    return __fdividef(1.0f, 1.0f + fexp(-x));
}
__device__ __forceinline__ float tf32r(float x) {
    uint32_t u;
    asm("cvt.rna.tf32.f32 %0, %1;" : "=r"(u) : "f"(x));
    return __uint_as_float(u);
}
__device__ __forceinline__ void mma8(float* d, const float* a, float b0f, float b1f) {
    const uint32_t* A = (const uint32_t*)a;
    uint32_t B0 = __float_as_uint(b0f), B1 = __float_as_uint(b1f);
    asm volatile(
        "mma.sync.aligned.m16n8k8.row.col.f32.tf32.tf32.f32 "
        "{%0,%1,%2,%3}, {%4,%5,%6,%7}, {%8,%9}, {%0,%1,%2,%3};\n"
        : "+f"(d[0]), "+f"(d[1]), "+f"(d[2]), "+f"(d[3])
        : "r"(A[0]), "r"(A[1]), "r"(A[2]), "r"(A[3]), "r"(B0), "r"(B1));
}

// ----------------------------- pack / convert kernels -----------------------------
__global__ void pack_s12(const float* __restrict__ s1w, const float* __restrict__ s2w,
                         const float* __restrict__ s1b, const float* __restrict__ s2b,
                         float* __restrict__ wi, float* __restrict__ bi) {
    int i = blockIdx.x * 256 + threadIdx.x;
    if (i < NDsz * Dsz) {
        int k = i >> 10, f = i & 1023;
        float2 v; v.x = tf32r(s1w[i]); v.y = tf32r(s2w[i]);
        *(float2*)(wi + (size_t)k * 2048 + 2 * f) = v;
    }
    if (i < Dsz) { bi[2 * i] = s1b[i]; bi[2 * i + 1] = s2b[i]; }
}
__global__ void pack_qkvg(const float* __restrict__ qw, const float* __restrict__ kw,
                          const float* __restrict__ vw, const float* __restrict__ gw,
                          const float* __restrict__ qb, const float* __restrict__ kb,
                          const float* __restrict__ vb, const float* __restrict__ gb2,
                          float* __restrict__ w, float* __restrict__ bb) {
    int i = blockIdx.x * 256 + threadIdx.x;
    if (i < Dsz * Dsz) {
        int r = i >> 10, c = i & 1023;
        float* o = w + (size_t)r * 4096;
        o[c]        = tf32r(qw[i]);
        o[1024 + c] = tf32r(kw[i]);
        o[2048 + c] = tf32r(vw[i]);
        o[3072 + c] = tf32r(gw[i]);
    }
    if (i < Dsz) {
        bb[i]        = qb[i];
        bb[1024 + i] = kb[i];
        bb[2048 + i] = vb[i];
        bb[3072 + i] = gb2[i];
    }
}
__global__ void cvt_all(const float* __restrict__ ow, float* __restrict__ dow,
                        const float* __restrict__ opw, float* __restrict__ dopw,
                        const float* __restrict__ s, float* __restrict__ dsr) {
    int i = blockIdx.x * 256 + threadIdx.x;
    if (i < Dsz * Dsz)   dow[i]  = tf32r(ow[i]);
    if (i < NDsz * Dsz)  dopw[i] = tf32r(opw[i]);
    if (i < Bsz * Lsz * NDsz) dsr[i] = tf32r(s[i]);
}

// ----------------------------- LayerNorm -----------------------------
__global__ void ln_kernel(const float* __restrict__ x, const float* __restrict__ g,
                          const float* __restrict__ b, float* __restrict__ y, int C, int rnd) {
    __shared__ float red[64];
    const int row = blockIdx.x;
    const float* xr = x + (size_t)row * C;
    float sum = 0.f, sq = 0.f;
    for (int i = threadIdx.x; i < C; i += 256) {
        float v = xr[i];
        sum += v; sq += v * v;
    }
    #pragma unroll
    for (int off = 16; off; off >>= 1) {
        sum += __shfl_xor_sync(0xffffffffu, sum, off);
        sq  += __shfl_xor_sync(0xffffffffu, sq,  off);
    }
    int w = threadIdx.x >> 5, lane = threadIdx.x & 31;
    if (lane == 0) { red[w] = sum; red[w + 32] = sq; }
    __syncthreads();
    if (w == 0) {
        float s1 = (lane < 8) ? red[lane] : 0.f;
        float s2 = (lane < 8) ? red[lane + 32] : 0.f;
        #pragma unroll
        for (int off = 4; off; off >>= 1) {
            s1 += __shfl_xor_sync(0xffffffffu, s1, off);
            s2 += __shfl_xor_sync(0xffffffffu, s2, off);
        }
        if (lane == 0) { red[0] = s1; red[1] = s2; }
    }
    __syncthreads();
    float mean = red[0] / (float)C;
    float var  = red[1] / (float)C - mean * mean;
    float inv  = rsqrtf(var + 1e-5f);
    float* yr = y + (size_t)row * C;
    for (int i = threadIdx.x; i < C; i += 256) {
        float v = (xr[i] - mean) * inv;
        if (g) v = v * g[i] + b[i];
        yr[i] = rnd ? tf32r(v) : v;
    }
}

// ----------------------------- tf32 GEMM 64x128x16, 128 threads, 4 blocks/SM -----------------
// EPI 0: C = A@B + bias
// EPI 1: C = sigmoid(A@B + bias)
// EPI 3: h2 = tf32r(sigmoid(even+bE)*aux + (odd+bO))     (interleaved; C,aux stride N/2)
// EPI 4: like 0 but rounds output for cols < 3*N/4 (q,k,v rounded; gate raw)
// EPI 5: C = (A@B + bias) * aux                          (final output gate multiply)
template<int EPI>
__global__ void __launch_bounds__(128, 4)
gemm_tf32(const float* __restrict__ A, const float* __restrict__ B,
          const float* __restrict__ bias, float* __restrict__ C,
          const float* __restrict__ aux, int M, int N, int K) {
    __shared__ __align__(16) float As[2][64][20];
    __shared__ __align__(16) float Bs[2][16][136];
    const int tid  = threadIdx.x;
    const int wid  = tid >> 5, lane = tid & 31;
    const int g    = lane >> 2, t4 = lane & 3;
    const int wm   = (wid & 1) * 32;
    const int wn   = (wid >> 1) * 64;
    const int bx   = blockIdx.x, by = blockIdx.y;

    const int ar = tid >> 2, ac = (tid & 3) * 4;
    const int br = tid >> 5, bc = (tid & 31) * 4;
    const float* Ag = A + ((size_t)(by * 64 + ar)) * K + ac;
    const float* Bg = B + (size_t)br * N + bx * 128 + bc;

    float acc[2][8][4];
    #pragma unroll
    for (int mt = 0; mt < 2; mt++)
        #pragma unroll
        for (int nt = 0; nt < 8; nt++)
            #pragma unroll
            for (int c = 0; c < 4; c++) acc[mt][nt][c] = 0.f;

    float4 ra0, ra1, rb[4];
    ra0 = *(const float4*)(Ag);
    ra1 = *(const float4*)(Ag + (size_t)32 * K);
    #pragma unroll
    for (int i = 0; i < 4; i++)
        rb[i] = *(const float4*)(Bg + (size_t)(4 * i) * N);

    *(float4*)&As[0][ar][ac]      = ra0;
    *(float4*)&As[0][ar + 32][ac] = ra1;
    #pragma unroll
    for (int i = 0; i < 4; i++)
        *(float4*)&Bs[0][br + 4 * i][bc] = rb[i];
    __syncthreads();

    const int nk = K >> 4;
    for (int it = 0; it < nk; it++) {
        const int buf = it & 1;
        if (it + 1 < nk) {
            const float* Ag2 = Ag + (it + 1) * 16;
            ra0 = *(const float4*)(Ag2);
            ra1 = *(const float4*)(Ag2 + (size_t)32 * K);
            const float* Bg2 = Bg + (size_t)(it + 1) * 16 * N;
            #pragma unroll
            for (int i = 0; i < 4; i++)
                rb[i] = *(const float4*)(Bg2 + (size_t)(4 * i) * N);
        }
        #pragma unroll
        for (int ks = 0; ks < 2; ks++) {
            const int k0 = ks * 8;
            float a[2][4];
            #pragma unroll
            for (int mt = 0; mt < 2; mt++) {
                const int m0 = wm + mt * 16;
                a[mt][0] = As[buf][m0 + g][k0 + t4];
                a[mt][1] = As[buf][m0 + g + 8][k0 + t4];
                a[mt][2] = As[buf][m0 + g][k0 + t4 + 4];
                a[mt][3] = As[buf][m0 + g + 8][k0 + t4 + 4];
            }
            #pragma unroll
            for (int nt = 0; nt < 8; nt++) {
                const float b0 = Bs[buf][k0 + t4][wn + nt * 8 + g];
                const float b1 = Bs[buf][k0 + t4 + 4][wn + nt * 8 + g];
                mma8(acc[0][nt], a[0], b0, b1);
                mma8(acc[1][nt], a[1], b0, b1);
            }
        }
        if (it + 1 < nk) {
            const int nb = buf ^ 1;
            *(float4*)&As[nb][ar][ac]      = ra0;
            *(float4*)&As[nb][ar + 32][ac] = ra1;
            #pragma unroll
            for (int i = 0; i < 4; i++)
                *(float4*)&Bs[nb][br + 4 * i][bc] = rb[i];
        }
        __syncthreads();
    }

    #pragma unroll
    for (int mt = 0; mt < 2; mt++) {
        #pragma unroll
        for (int nt = 0; nt < 8; nt++) {
            const int row0 = by * 64 + wm + mt * 16 + g;
            const int col  = bx * 128 + wn + nt * 8 + 2 * t4;
            const float b0 = bias[col], b1 = bias[col + 1];
            if (EPI == 3) {
                const int f = col >> 1;
                const int ldc = N >> 1;
                float e0 = acc[mt][nt][0] + b0, o0 = acc[mt][nt][1] + b1;
                float e1 = acc[mt][nt][2] + b0, o1 = acc[mt][nt][3] + b1;
                C[(size_t)row0 * ldc + f]       = tf32r(sigmoidf_(e0) * aux[(size_t)row0 * ldc + f] + o0);
                C[(size_t)(row0 + 8) * ldc + f] = tf32r(sigmoidf_(e1) * aux[(size_t)(row0 + 8) * ldc + f] + o1);
            } else {
                float2 o0, o1;
                o0.x = acc[mt][nt][0] + b0; o0.y = acc[mt][nt][1] + b1;
                o1.x = acc[mt][nt][2] + b0; o1.y = acc[mt][nt][3] + b1;
                if (EPI == 1) {
                    o0.x = sigmoidf_(o0.x); o0.y = sigmoidf_(o0.y);
                    o1.x = sigmoidf_(o1.x); o1.y = sigmoidf_(o1.y);
                } else if (EPI == 5) {
                    float2 x0 = *(const float2*)(aux + (size_t)row0 * N + col);
                    float2 x1 = *(const float2*)(aux + (size_t)(row0 + 8) * N + col);
                    o0.x *= x0.x; o0.y *= x0.y;
                    o1.x *= x1.x; o1.y *= x1.y;
                } else if (EPI == 4) {
                    if (col < (3 * N) / 4) {
                        o0.x = tf32r(o0.x); o0.y = tf32r(o0.y);
                        o1.x = tf32r(o1.x); o1.y = tf32r(o1.y);
                    }
                }
                *(float2*)(C + (size_t)row0 * N + col)       = o0;
                *(float2*)(C + (size_t)(row0 + 8) * N + col) = o1;
            }
        }
    }
}

// ----------------------------- V transpose: packed qkvg v-slice -> [B][D][L] ---------------------
__global__ void transpose_kernel(const float* __restrict__ src, float* __restrict__ dst) {
    __shared__ float tile[32][33];
    const int b = blockIdx.z;
    const int x0 = blockIdx.x * 32;
    const int y0 = blockIdx.y * 32;
    const int tx = threadIdx.x, ty = threadIdx.y;
    #pragma unroll
    for (int i = 0; i < 32; i += 8)
        tile[ty + i][tx] = src[((size_t)b * Lsz + y0 + ty + i) * 4096 + x0 + tx];
    __syncthreads();
    #pragma unroll
    for (int i = 0; i < 32; i += 8)
        dst[((size_t)b * Dsz + x0 + ty + i) * Lsz + y0 + tx] = tile[tx][ty + i];
}

// ----------------------------- pair bias via tensor cores -----------------------------
__global__ void __launch_bounds__(128)
pairbias_mma(const float* __restrict__ p, const float* __restrict__ eg,
             const float* __restrict__ eb, const float* __restrict__ ew,
             float* __restrict__ bias) {
    __shared__ __align__(16) float xs[128 * 68];
    __shared__ float sew[Esz * Hsz];
    __shared__ float seg[Esz], seb[Esz];
    const int tid = threadIdx.x, wid = tid >> 5, lane = tid & 31;
    const int g = lane >> 2, t4 = lane & 3;
    const int b = blockIdx.z, i = blockIdx.y, j0 = blockIdx.x * 128;

    float4 pr[16];
    const float4* prow = (const float4*)(p + (((size_t)b * Lsz + i) * Lsz + j0 + tid) * Esz);
    #pragma unroll
    for (int c = 0; c < 16; c++) pr[c] = prow[c];

    for (int t = tid; t < Esz * Hsz; t += 128) sew[t] = tf32r(ew[t]);
    if (tid < Esz) { seg[tid] = eg[tid]; seb[tid] = eb[tid]; }
    __syncthreads();

    float sum = 0.f, sq = 0.f;
    #pragma unroll
    for (int c = 0; c < 16; c++) {
        sum += pr[c].x + pr[c].y + pr[c].z + pr[c].w;
        sq  += pr[c].x * pr[c].x + pr[c].y * pr[c].y + pr[c].z * pr[c].z + pr[c].w * pr[c].w;
    }
    float mean = sum * (1.f / 64.f);
    float var  = sq * (1.f / 64.f) - mean * mean;
    float inv  = rsqrtf(var + 1e-5f);

    float* xrow = xs + tid * 68;
    #pragma unroll
    for (int c = 0; c < 16; c++) {
        float4 o;
        int e = c * 4;
        o.x = tf32r((pr[c].x - mean) * inv * seg[e + 0] + seb[e + 0]);
        o.y = tf32r((pr[c].y - mean) * inv * seg[e + 1] + seb[e + 1]);
        o.z = tf32r((pr[c].z - mean) * inv * seg[e + 2] + seb[e + 2]);
        o.w = tf32r((pr[c].w - mean) * inv * seg[e + 3] + seb[e + 3]);
        *(float4*)(xrow + e) = o;
    }
    __syncthreads();

    float acc[2][2][4];
    #pragma unroll
    for (int m = 0; m < 2; m++)
        #pragma unroll
        for (int n = 0; n < 2; n++)
            #pragma unroll
            for (int c = 0; c < 4; c++) acc[m][n][c] = 0.f;

    #pragma unroll
    for (int k = 0; k < 8; k++) {
        const int k0 = k * 8;
        float a[2][4];
        #pragma unroll
        for (int m = 0; m < 2; m++) {
            const int m0 = wid * 32 + m * 16;
            a[m][0] = xs[(m0 + g) * 68 + k0 + t4];
            a[m][1] = xs[(m0 + g + 8) * 68 + k0 + t4];
            a[m][2] = xs[(m0 + g) * 68 + k0 + t4 + 4];
            a[m][3] = xs[(m0 + g + 8) * 68 + k0 + t4 + 4];
        }
        #pragma unroll
        for (int n = 0; n < 2; n++) {
            const float b0 = sew[(k0 + t4) * 16 + n * 8 + g];
            const float b1 = sew[(k0 + t4 + 4) * 16 + n * 8 + g];
            mma8(acc[0][n], a[0], b0, b1);
            mma8(acc[1][n], a[1], b0, b1);
        }
    }

    const size_t LL = (size_t)Lsz * Lsz;
    #pragma unroll
    for (int m = 0; m < 2; m++) {
        const int jg = j0 + wid * 32 + m * 16 + g;
        #pragma unroll
        for (int n = 0; n < 2; n++) {
            const int h0 = n * 8 + 2 * t4;
            size_t base = ((size_t)(b * Hsz + h0) * Lsz + i) * Lsz;
            bias[base + jg]          = acc[m][n][0];
            bias[base + LL + jg]     = acc[m][n][1];
            bias[base + jg + 8]      = acc[m][n][2];
            bias[base + LL + jg + 8] = acc[m][n][3];
        }
    }
}

// ----------------------------- flash attention (double-buffered K/V, Q direct, 2 blk/SM) -----
#define ATTN_SMEM ((4 * 4352 + 128 * 68) * 4)   // K[2]+V[2] + Ps(P only) = 104448 B
__global__ void __launch_bounds__(256, 2)
attn_mma(const float* __restrict__ qkvg, const float* __restrict__ vt,
         const float* __restrict__ bias, float* __restrict__ y) {
    extern __shared__ __align__(16) float smx[];
    float* Ps = smx + 17408;   // [128][68] P staging

    const int b = blockIdx.z, hh = blockIdx.y, i0 = blockIdx.x * 128;
    const int tid = threadIdx.x, wid = tid >> 5, lane = tid & 31;
    const int g = lane >> 2, t4 = lane & 3;
    const int wr0 = wid * 16;
    const int sr = tid >> 4, sc = (tid & 15) * 4;

    // Q fragments directly from gmem (q pre-rounded tf32; *2^-3 exact)
    float qa[8][4];
    {
        const float* qrow0 = qkvg + ((size_t)(b * Lsz) + i0 + wr0 + g) * 4096 + hh * 64;
        const float* qrow1 = qrow0 + (size_t)8 * 4096;
        #pragma unroll
        for (int kt = 0; kt < 8; kt++) {
            qa[kt][0] = qrow0[kt * 8 + t4] * QSCALE;
            qa[kt][1] = qrow1[kt * 8 + t4] * QSCALE;
            qa[kt][2] = qrow0[kt * 8 + t4 + 4] * QSCALE;
            qa[kt][3] = qrow1[kt * 8 + t4 + 4] * QSCALE;
        }
    }
    float oacc[8][4];
    #pragma unroll
    for (int nt = 0; nt < 8; nt++)
        #pragma unroll
        for (int c = 0; c < 4; c++) oacc[nt][c] = 0.f;
    float m0 = -1e30f, m1 = -1e30f, l0 = 0.f, l1 = 0.f;

    const float* brow0 = bias + (((size_t)(b * Hsz + hh)) * Lsz + i0 + wr0 + g) * Lsz;
    const float* brow1 = brow0 + (size_t)8 * Lsz;
    const float* kbase = qkvg + (size_t)(b * Lsz) * 4096 + 1024 + hh * 64;
    const float* vbase = vt + ((size_t)(b * Dsz) + hh * 64) * Lsz;

    // stage tile 0 into buffer 0
    for (int rr = sr; rr < 64; rr += 16) {
        float4 kv = *(const float4*)(kbase + (size_t)rr * 4096 + sc);
        *(float4*)(smx + rr * 68 + sc) = kv;
        float4 vv = *(const float4*)(vbase + (size_t)rr * Lsz + sc);
        *(float4*)(smx + 8704 + rr * 68 + sc) = vv;
    }
    __syncthreads();

    for (int jt = 0; jt < 16; jt++) {
        const int jb = jt * 64;
        const int buf = jt & 1;
        float* Ks = smx + buf * 4352;
        float* Vs = smx + 8704 + buf * 4352;

        // issue next tile's copy into the free buffer (drains under compute)
        if (jt + 1 < 16) {
            float* Kn = smx + (buf ^ 1) * 4352;
            float* Vn = smx + 8704 + (buf ^ 1) * 4352;
            const int jn = jb + 64;
            for (int rr = sr; rr < 64; rr += 16) {
                float4 kv = *(const float4*)(kbase + (size_t)(jn + rr) * 4096 + sc);
                *(float4*)(Kn + rr * 68 + sc) = kv;
                float4 vv = *(const float4*)(vbase + (size_t)rr * Lsz + jn + sc);
                *(float4*)(Vn + rr * 68 + sc) = vv;
            }
        }

        // S = Q K^T + bias
        float sacc[8][4];
        #pragma unroll
        for (int nt = 0; nt < 8; nt++) {
            float2 bb0 = *(const float2*)(brow0 + jb + nt * 8 + 2 * t4);
            float2 bb1 = *(const float2*)(brow1 + jb + nt * 8 + 2 * t4);
            sacc[nt][0] = bb0.x; sacc[nt][1] = bb0.y;
            sacc[nt][2] = bb1.x; sacc[nt][3] = bb1.y;
        }
        #pragma unroll
        for (int kt = 0; kt < 8; kt++) {
            const int k0 = kt * 8;
            #pragma unroll
            for (int nt = 0; nt < 8; nt++) {
                const float b0 = Ks[(nt * 8 + g) * 68 + k0 + t4];
                const float b1 = Ks[(nt * 8 + g) * 68 + k0 + t4 + 4];
                mma8(sacc[nt], qa[kt], b0, b1);
            }
        }
        // online softmax
        float mx0 = -1e30f, mx1 = -1e30f;
        #pragma unroll
        for (int nt = 0; nt < 8; nt++) {
            mx0 = fmaxf(mx0, fmaxf(sacc[nt][0], sacc[nt][1]));
            mx1 = fmaxf(mx1, fmaxf(sacc[nt][2], sacc[nt][3]));
        }
        mx0 = fmaxf(mx0, __shfl_xor_sync(0xffffffffu, mx0, 1));
        mx0 = fmaxf(mx0, __shfl_xor_sync(0xffffffffu, mx0, 2));
        mx1 = fmaxf(mx1, __shfl_xor_sync(0xffffffffu, mx1, 1));
        mx1 = fmaxf(mx1, __shfl_xor_sync(0xffffffffu, mx1, 2));
        const float nm0 = fmaxf(m0, mx0), nm1 = fmaxf(m1, mx1);
        const float c0 = fexp(m0 - nm0), c1 = fexp(m1 - nm1);
        m0 = nm0; m1 = nm1;
        float rs0 = 0.f, rs1 = 0.f;
        #pragma unroll
        for (int nt = 0; nt < 8; nt++) {
            float p0 = fexp(sacc[nt][0] - nm0);
            float p1 = fexp(sacc[nt][1] - nm0);
            float p2 = fexp(sacc[nt][2] - nm1);
            float p3 = fexp(sacc[nt][3] - nm1);
            rs0 += p0 + p1; rs1 += p2 + p3;
            float* pr0 = Ps + (wr0 + g) * 68 + nt * 8 + 2 * t4;
            pr0[0] = tf32r(p0); pr0[1] = tf32r(p1);
            float* pr1 = Ps + (wr0 + g + 8) * 68 + nt * 8 + 2 * t4;
            pr1[0] = tf32r(p2); pr1[1] = tf32r(p3);
            oacc[nt][0] *= c0; oacc[nt][1] *= c0;
            oacc[nt][2] *= c1; oacc[nt][3] *= c1;
        }
        rs0 += __shfl_xor_sync(0xffffffffu, rs0, 1);
        rs0 += __shfl_xor_sync(0xffffffffu, rs0, 2);
        rs1 += __shfl_xor_sync(0xffffffffu, rs1, 1);
        rs1 += __shfl_xor_sync(0xffffffffu, rs1, 2);
        l0 = l0 * c0 + rs0;
        l1 = l1 * c1 + rs1;
        __syncwarp();

        // O += P V
        #pragma unroll
        for (int kt = 0; kt < 8; kt++) {
            const int k0 = kt * 8;
            float pa[4];
            pa[0] = Ps[(wr0 + g) * 68 + k0 + t4];
            pa[1] = Ps[(wr0 + g + 8) * 68 + k0 + t4];
            pa[2] = Ps[(wr0 + g) * 68 + k0 + t4 + 4];
            pa[3] = Ps[(wr0 + g + 8) * 68 + k0 + t4 + 4];
            #pragma unroll
            for (int nt = 0; nt < 8; nt++) {
                const float b0 = Vs[(nt * 8 + g) * 68 + k0 + t4];
                const float b1 = Vs[(nt * 8 + g) * 68 + k0 + t4 + 4];
                mma8(oacc[nt], pa, b0, b1);
            }
        }
        __syncthreads();   // next-buffer stores visible; this buffer free for jt+2
    }

    const float inv0 = __fdividef(1.f, l0), inv1 = __fdividef(1.f, l1);
    #pragma unroll
    for (int nt = 0; nt < 8; nt++) {
        const int col = hh * 64 + nt * 8 + 2 * t4;
        size_t gr0 = ((size_t)(b * Lsz) + i0 + wr0 + g) * 4096 + 3072 + col;
        size_t gr1 = gr0 + (size_t)8 * 4096;
        float2 gv0 = *(const float2*)(qkvg + gr0);
        float2 gv1 = *(const float2*)(qkvg + gr1);
        size_t r0 = ((size_t)(b * Lsz) + i0 + wr0 + g) * Dsz + col;
        size_t r1 = r0 + (size_t)8 * Dsz;
        float2 o0, o1;
        o0.x = tf32r(oacc[nt][0] * inv0 * sigmoidf_(gv0.x));
        o0.y = tf32r(oacc[nt][1] * inv0 * sigmoidf_(gv0.y));
        o1.x = tf32r(oacc[nt][2] * inv1 * sigmoidf_(gv1.x));
        o1.y = tf32r(oacc[nt][3] * inv1 * sigmoidf_(gv1.y));
        *(float2*)(y + r0) = o0;
        *(float2*)(y + r1) = o1;
    }
}

// ----------------------------- launch -----------------------------
static cudaStream_t s_stream2 = nullptr;
static cudaEvent_t  s_evFork = nullptr, s_evJoin = nullptr;

extern "C" void kernel_launch(void* const* d_in, const int* in_sizes, int n_in,
                              void* d_out, int out_size) {
    const float* h     = (const float*)d_in[0];
    const float* p     = (const float*)d_in[1];
    const float* s     = (const float*)d_in[2];
    const float* sln_g = (const float*)d_in[3];
    const float* sln_b = (const float*)d_in[4];
    const float* s1_w  = (const float*)d_in[5];
    const float* s1_b  = (const float*)d_in[6];
    const float* s2_w  = (const float*)d_in[7];
    const float* s2_b  = (const float*)d_in[8];
    const float* q_w   = (const float*)d_in[9];
    const float* q_b   = (const float*)d_in[10];
    const float* k_w   = (const float*)d_in[11];
    const float* k_b   = (const float*)d_in[12];
    const float* v_w   = (const float*)d_in[13];
    const float* v_b   = (const float*)d_in[14];
    const float* eln_g = (const float*)d_in[15];
    const float* eln_b = (const float*)d_in[16];
    const float* e_w   = (const float*)d_in[17];
    const float* gw    = (const float*)d_in[18];
    const float* gb    = (const float*)d_in[19];
    const float* o_w   = (const float*)d_in[20];
    const float* o_b   = (const float*)d_in[21];
    const float* op_w  = (const float*)d_in[22];
    const float* op_b  = (const float*)d_in[23];
    float* out = (float*)d_out;

    float *hn, *sn, *h2, *qkvg, *vtp, *yp, *gatep, *biasp;
    float *wqkvg, *bqkvg, *ws12i, *bs12i, *wo, *wop, *sr;
    cudaGetSymbolAddress((void**)&hn,    g_hn);
    cudaGetSymbolAddress((void**)&sn,    g_sn);
    cudaGetSymbolAddress((void**)&h2,    g_h2);
    cudaGetSymbolAddress((void**)&qkvg,  g_qkvg);
    cudaGetSymbolAddress((void**)&vtp,   g_vt);
    cudaGetSymbolAddress((void**)&yp,    g_yb);
    cudaGetSymbolAddress((void**)&gatep, g_gate);
    cudaGetSymbolAddress((void**)&biasp, g_bias);
    cudaGetSymbolAddress((void**)&wqkvg, g_wqkvg);
    cudaGetSymbolAddress((void**)&bqkvg, g_bqkvg);
    cudaGetSymbolAddress((void**)&ws12i, g_ws12i);
    cudaGetSymbolAddress((void**)&bs12i, g_bs12i);
    cudaGetSymbolAddress((void**)&wo,    g_wo);
    cudaGetSymbolAddress((void**)&wop,   g_wop);
    cudaGetSymbolAddress((void**)&sr,    g_sr);

    if (!s_stream2) {
        cudaStreamCreateWithFlags(&s_stream2, cudaStreamNonBlocking);
        cudaEventCreateWithFlags(&s_evFork, cudaEventDisableTiming);
        cudaEventCreateWithFlags(&s_evJoin, cudaEventDisableTiming);
        cudaFuncSetAttribute(attn_mma, cudaFuncAttributeMaxDynamicSharedMemorySize, ATTN_SMEM);
    }

    const int M = Bsz * Lsz;           // 2048

    // ---- fork: stream B runs pairbias (tensor-core version) alone ----
    cudaEventRecord(s_evFork, 0);
    cudaStreamWaitEvent(s_stream2, s_evFork, 0);
    pairbias_mma<<<dim3(Lsz / 128, Lsz, Bsz), 128, 0, s_stream2>>>(p, eln_g, eln_b, e_w, biasp);
    cudaEventRecord(s_evJoin, s_stream2);

    // ---- stream A (default): everything else ----
    pack_s12<<<(NDsz * Dsz + 255) / 256, 256>>>(s1_w, s2_w, s1_b, s2_b, ws12i, bs12i);
    pack_qkvg<<<(Dsz * Dsz + 255) / 256, 256>>>(q_w, k_w, v_w, gw, q_b, k_b, v_b, gb, wqkvg, bqkvg);
    cvt_all<<<(Dsz * Dsz + 255) / 256, 256>>>(o_w, wo, op_w, wop, s, sr);

    ln_kernel<<<M, 256>>>(h, nullptr, nullptr, hn, Dsz, 0);
    ln_kernel<<<M, 256>>>(s, sln_g, sln_b, sn, NDsz, 1);

    gemm_tf32<3><<<dim3(2048 / 128, M / 64), 128>>>(sn, ws12i, bs12i, h2, hn, M, 2048, NDsz);
    gemm_tf32<4><<<dim3(4096 / 128, M / 64), 128>>>(h2, wqkvg, bqkvg, qkvg, nullptr, M, 4096, Dsz);
    transpose_kernel<<<dim3(32, 32, Bsz), dim3(32, 8)>>>(qkvg + 2048, vtp);
    gemm_tf32<1><<<dim3(Dsz / 128, M / 64), 128>>>(sr, wop, op_b, gatep, nullptr, M, Dsz, NDsz);

    // ---- join: attention needs pairbias ----
    cudaStreamWaitEvent(0, s_evJoin, 0);

    attn_mma<<<dim3(Lsz / 128, Hsz, Bsz), 256, ATTN_SMEM>>>(qkvg, vtp, biasp, yp);

    // o-projection with fused final gate multiply -> out
    gemm_tf32<5><<<dim3(Dsz / 128, M / 64), 128>>>(yp, wo, o_b, out, gatep, M, Dsz, Dsz);
}